// round 13
// baseline (speedup 1.0000x reference)
#include <cuda_runtime.h>
#include <cuda_fp16.h>
#include <cstdint>
#include <cstddef>

#define NSEQ 512
#define DDIM 128
#define NN   (NSEQ*NSEQ)

// Scratch
static __device__ __half g_af[(size_t)DDIM * NN];
static __device__ __half g_bf[(size_t)DDIM * NN];
static __device__ float  g_t[(size_t)DDIM * NN];
static __device__ __half g_gate[(size_t)NN * DDIM];

// Pre-converted weights (fp16), row-major [ch][k]; column sums of the fp16 weights
static __device__ __half g_wg[256*128];
static __device__ __half g_wp[256*128];
static __device__ __half g_og[128*128];
static __device__ __half g_oph[128*128];
static __device__ float  g_wbar[128];     // sums of fp16(opw)
static __device__ float  g_wgbar[256];
static __device__ float  g_wpbar[256];
static __device__ float  g_ogbar[128];

__device__ __forceinline__ float sigmoidf_(float x) { return 1.0f / (1.0f + __expf(-x)); }

__device__ __forceinline__ uint32_t smem_u32(const void* p) {
    uint32_t a;
    asm("{ .reg .u64 t; cvta.to.shared.u64 t, %1; cvt.u32.u64 %0, t; }" : "=r"(a) : "l"(p));
    return a;
}
#define SW128(o) ((o) ^ (((o) >> 3) & 0x70))

#define CP_ASYNC16(dst, src) \
    asm volatile("cp.async.cg.shared.global [%0], [%1], 16;" :: "r"(dst), "l"(src) : "memory")
#define CP_COMMIT() asm volatile("cp.async.commit_group;" ::: "memory")
#define CP_WAIT(n)  asm volatile("cp.async.wait_group %0;" :: "n"(n) : "memory")

__device__ __forceinline__ void ldm4(uint32_t addr, uint32_t r[4]) {
    asm volatile("ldmatrix.sync.aligned.m8n8.x4.shared.b16 {%0,%1,%2,%3}, [%4];"
        : "=r"(r[0]), "=r"(r[1]), "=r"(r[2]), "=r"(r[3]) : "r"(addr));
}
__device__ __forceinline__ void ldm4t(uint32_t addr, uint32_t r[4]) {
    asm volatile("ldmatrix.sync.aligned.m8n8.x4.trans.shared.b16 {%0,%1,%2,%3}, [%4];"
        : "=r"(r[0]), "=r"(r[1]), "=r"(r[2]), "=r"(r[3]) : "r"(addr));
}
__device__ __forceinline__ void mma16816(float c[4], const uint32_t a[4],
                                         uint32_t b0, uint32_t b1) {
    asm volatile(
        "mma.sync.aligned.m16n8k16.row.col.f32.f16.f16.f32 "
        "{%0,%1,%2,%3}, {%4,%5,%6,%7}, {%8,%9}, {%0,%1,%2,%3};"
        : "+f"(c[0]), "+f"(c[1]), "+f"(c[2]), "+f"(c[3])
        : "r"(a[0]), "r"(a[1]), "r"(a[2]), "r"(a[3]), "r"(b0), "r"(b1));
}

// ============================================================================
__global__ void __launch_bounds__(256) kW(
    const float* __restrict__ agw, const float* __restrict__ apw,
    const float* __restrict__ ogw, const float* __restrict__ opw)
{
    int i = blockIdx.x * 256 + threadIdx.x;
    if (i < 256*128) {
        g_wg[i] = __float2half_rn(agw[i]);
        g_wp[i] = __float2half_rn(apw[i]);
    }
    if (i < 128*128) {
        g_og[i]  = __float2half_rn(ogw[i]);
        g_oph[i] = __float2half_rn(opw[i]);
    }
}
// column sums of the fp16 weight matrices
__global__ void kWb(const float* __restrict__ agw, const float* __restrict__ apw,
                    const float* __restrict__ ogw, const float* __restrict__ opw)
{
    int c = threadIdx.x;   // 0..255
    float sg = 0.f, sp = 0.f;
    for (int d = 0; d < 128; d++) {
        sg += __half2float(__float2half_rn(agw[c*128 + d]));
        sp += __half2float(__float2half_rn(apw[c*128 + d]));
    }
    g_wgbar[c] = sg;
    g_wpbar[c] = sp;
    if (c < 128) {
        float so = 0.f, sw = 0.f;
        for (int d = 0; d < 128; d++) {
            so += __half2float(__float2half_rn(ogw[c*128 + d]));
            sw += __half2float(__float2half_rn(opw[c*128 + d]));
        }
        g_ogbar[c] = so;
        g_wbar[c]  = sw;
    }
}

// ============================================================================
// Kernel A (LN folded into epilogue, W pipelined, direct stores)
// smem: A(raw pair fp16) 32K @0 | W 2x32K @32768 | stats/mask @98304
// ============================================================================
__global__ void __launch_bounds__(256, 2) kA(
    const float* __restrict__ pair, const float* __restrict__ mask,
    const float* __restrict__ apb, const float* __restrict__ agb,
    const float* __restrict__ ogb)
{
    extern __shared__ char smc[];
    const uint32_t sbase = smem_u32(smc);
    const uint32_t uA = sbase;
    const uint32_t uW = sbase + 32768;
    float* pS    = (float*)(smc + 98304);          // [128][2]
    float* pQ    = (float*)(smc + 98304 + 1024);   // [128][2]
    float* sMu   = (float*)(smc + 98304 + 2048);   // [128]
    float* sRstd = (float*)(smc + 98304 + 2560);   // [128]
    float* sM    = (float*)(smc + 98304 + 3072);   // [128]

    const int t    = threadIdx.x;
    const int lane = t & 31;
    const int wid  = t >> 5;
    const int r0   = blockIdx.x * 128;

    auto prefetchW = [&](int stage, int c) {
        uint32_t sb = uW + stage * 32768;
        const __half* w0;
        const __half* w1 = nullptr;
        if (c < 4) { w0 = g_wg + (size_t)c*64*128; w1 = g_wp + (size_t)c*64*128; }
        else       { w0 = g_og + (size_t)(c - 4)*64*128; }
        #pragma unroll
        for (int q = 0; q < 4; q++) {
            int seg = t + 256*q;
            int ch  = seg >> 4;
            int s8  = seg & 15;
            uint32_t dst = ((s8 >= 8) ? 8192u : 0u) + SW128((uint32_t)(ch*128 + (s8 & 7)*16));
            CP_ASYNC16(sb + dst, w0 + (size_t)ch*128 + s8*8);
            if (w1) CP_ASYNC16(sb + 16384 + dst, w1 + (size_t)ch*128 + s8*8);
        }
        CP_COMMIT();
    };
    prefetchW(0, 0);

    if (t < 128) sM[t] = mask[r0 + t];

    // raw pair -> fp16 A tiles (row-major, no transpose), stats in registers
    {
        const int prow = t >> 1;            // 0..127
        const int dh   = (t & 1) * 64;      // k-half
        const float* src = pair + (size_t)(r0 + prow) * DDIM + dh;
        const uint32_t base = (dh ? 16384u : 0u);
        float s = 0.f, qq = 0.f;
        #pragma unroll
        for (int i = 0; i < 16; i++) {
            float4 f = *(const float4*)(src + i*4);
            s  += (f.x + f.y) + (f.z + f.w);
            qq += (f.x*f.x + f.y*f.y) + (f.z*f.z + f.w*f.w);
            __half2 hA = __halves2half2(__float2half_rn(f.x), __float2half_rn(f.y));
            __half2 hB = __halves2half2(__float2half_rn(f.z), __float2half_rn(f.w));
            uint32_t off = base + SW128((uint32_t)(prow*128 + i*8));
            *(__half2*)(smc + off)     = hA;
            *(__half2*)(smc + off + 4) = hB;
        }
        pS[prow*2 + (t & 1)] = s;
        pQ[prow*2 + (t & 1)] = qq;
    }
    __syncthreads();
    if (t < 128) {
        float ss = pS[t*2] + pS[t*2 + 1];
        float q2 = pQ[t*2] + pQ[t*2 + 1];
        float mu  = ss * (1.0f/128.0f);
        float var = q2 * (1.0f/128.0f) - mu*mu;
        sMu[t]   = mu;
        sRstd[t] = rsqrtf(var + 1e-5f);
    }

    const int aRow = lane & 15;
    const int aK   = (lane >> 4) * 16;
    const int bRow = (lane & 7) + ((lane >> 4) << 3);
    const int bK   = ((lane >> 3) & 1) * 16;
    const int m0   = (wid & 1) * 64;
    const int n0   = (wid >> 1) * 16;

    for (int c = 0; c < 6; c++) {
        const int stage = c & 1;
        if (c < 5) { prefetchW(stage ^ 1, c + 1); CP_WAIT(1); }
        else       { CP_WAIT(0); }
        __syncthreads();

        const uint32_t sW0 = uW + stage * 32768;
        const uint32_t sW1 = sW0 + 16384;
        const bool isAB = (c < 4);
        const int ch0   = isAB ? c * 64 : (c - 4) * 64;

        if (isAB) {
            float accg[4][2][4], accp[4][2][4];
            #pragma unroll
            for (int m = 0; m < 4; m++)
                #pragma unroll
                for (int n = 0; n < 2; n++)
                    #pragma unroll
                    for (int e = 0; e < 4; e++) { accg[m][n][e] = 0.f; accp[m][n][e] = 0.f; }

            #pragma unroll
            for (int kk = 0; kk < 8; kk++) {
                const uint32_t halfA = (uint32_t)(kk >> 2) * 16384u;
                const uint32_t halfW = (uint32_t)(kk >> 2) * 8192u;
                const uint32_t k32   = (uint32_t)(kk & 3) * 32u;

                uint32_t ah[4][4];
                #pragma unroll
                for (int f = 0; f < 4; f++) {
                    uint32_t off = SW128((uint32_t)((m0 + f*16 + aRow)*128) + k32 + aK);
                    ldm4(uA + halfA + off, ah[f]);
                }
                uint32_t gh[4], ph[4];
                {
                    uint32_t off = SW128((uint32_t)((n0 + bRow)*128) + k32 + bK);
                    ldm4(sW0 + halfW + off, gh);
                    ldm4(sW1 + halfW + off, ph);
                }
                #pragma unroll
                for (int m = 0; m < 4; m++)
                    #pragma unroll
                    for (int n = 0; n < 2; n++) {
                        mma16816(accg[m][n], ah[m], gh[n*2], gh[n*2+1]);
                        mma16816(accp[m][n], ah[m], ph[n*2], ph[n*2+1]);
                    }
            }

            __half* dst = (ch0 < 128) ? (g_af + (size_t)ch0 * NN)
                                      : (g_bf + (size_t)(ch0 - 128) * NN);
            #pragma unroll
            for (int m = 0; m < 4; m++) {
                int row0 = m0 + m*16 + (lane >> 2);
                float mu0 = sMu[row0],   rs0 = sRstd[row0];
                float mu1 = sMu[row0+8], rs1 = sRstd[row0+8];
                float mv0 = sM[row0],    mv1 = sM[row0 + 8];
                #pragma unroll
                for (int n = 0; n < 2; n++) {
                    int c0 = n0 + n*8 + (lane & 3)*2;
                    float gb0 = __ldg(agb + ch0 + c0),   gb1 = __ldg(agb + ch0 + c0 + 1);
                    float pb0 = __ldg(apb + ch0 + c0),   pb1 = __ldg(apb + ch0 + c0 + 1);
                    float wg0 = __ldg(g_wgbar + ch0 + c0), wg1 = __ldg(g_wgbar + ch0 + c0 + 1);
                    float wp0 = __ldg(g_wpbar + ch0 + c0), wp1 = __ldg(g_wpbar + ch0 + c0 + 1);
                    float v00 = mv0 * sigmoidf_(rs0*(accg[m][n][0] - mu0*wg0) + gb0)
                                    * (rs0*(accp[m][n][0] - mu0*wp0) + pb0);
                    float v01 = mv0 * sigmoidf_(rs0*(accg[m][n][1] - mu0*wg1) + gb1)
                                    * (rs0*(accp[m][n][1] - mu0*wp1) + pb1);
                    float v10 = mv1 * sigmoidf_(rs1*(accg[m][n][2] - mu1*wg0) + gb0)
                                    * (rs1*(accp[m][n][2] - mu1*wp0) + pb0);
                    float v11 = mv1 * sigmoidf_(rs1*(accg[m][n][3] - mu1*wg1) + gb1)
                                    * (rs1*(accp[m][n][3] - mu1*wp1) + pb1);
                    __half* p0 = dst + (size_t)c0 * NN + r0 + row0;
                    __half* p1 = dst + (size_t)(c0 + 1) * NN + r0 + row0;
                    p0[0] = __float2half_rn(v00);
                    p1[0] = __float2half_rn(v01);
                    p0[8] = __float2half_rn(v10);
                    p1[8] = __float2half_rn(v11);
                }
            }
        } else {
            float accg[4][2][4];
            #pragma unroll
            for (int m = 0; m < 4; m++)
                #pragma unroll
                for (int n = 0; n < 2; n++)
                    #pragma unroll
                    for (int e = 0; e < 4; e++) accg[m][n][e] = 0.f;

            #pragma unroll
            for (int kk = 0; kk < 8; kk++) {
                const uint32_t halfA = (uint32_t)(kk >> 2) * 16384u;
                const uint32_t halfW = (uint32_t)(kk >> 2) * 8192u;
                const uint32_t k32   = (uint32_t)(kk & 3) * 32u;

                uint32_t ah[4][4];
                #pragma unroll
                for (int f = 0; f < 4; f++) {
                    uint32_t off = SW128((uint32_t)((m0 + f*16 + aRow)*128) + k32 + aK);
                    ldm4(uA + halfA + off, ah[f]);
                }
                uint32_t gh[4];
                {
                    uint32_t off = SW128((uint32_t)((n0 + bRow)*128) + k32 + bK);
                    ldm4(sW0 + halfW + off, gh);
                }
                #pragma unroll
                for (int m = 0; m < 4; m++)
                    #pragma unroll
                    for (int n = 0; n < 2; n++)
                        mma16816(accg[m][n], ah[m], gh[n*2], gh[n*2+1]);
            }

            #pragma unroll
            for (int m = 0; m < 4; m++) {
                int row0 = m0 + m*16 + (lane >> 2);
                float mu0 = sMu[row0],   rs0 = sRstd[row0];
                float mu1 = sMu[row0+8], rs1 = sRstd[row0+8];
                #pragma unroll
                for (int n = 0; n < 2; n++) {
                    int c0 = n0 + n*8 + (lane & 3)*2;
                    float gb0 = __ldg(ogb + ch0 + c0),     gb1 = __ldg(ogb + ch0 + c0 + 1);
                    float wo0 = __ldg(g_ogbar + ch0 + c0), wo1 = __ldg(g_ogbar + ch0 + c0 + 1);
                    __half2 h0 = __halves2half2(
                        __float2half_rn(sigmoidf_(rs0*(accg[m][n][0] - mu0*wo0) + gb0)),
                        __float2half_rn(sigmoidf_(rs0*(accg[m][n][1] - mu0*wo1) + gb1)));
                    __half2 h1 = __halves2half2(
                        __float2half_rn(sigmoidf_(rs1*(accg[m][n][2] - mu1*wo0) + gb0)),
                        __float2half_rn(sigmoidf_(rs1*(accg[m][n][3] - mu1*wo1) + gb1)));
                    *(__half2*)(g_gate + (size_t)(r0 + row0)*DDIM + ch0 + c0)     = h0;
                    *(__half2*)(g_gate + (size_t)(r0 + row0 + 8)*DDIM + ch0 + c0) = h1;
                }
            }
        }
        __syncthreads();
    }
}

// ============================================================================
// Kernel B (fp16 1-term) — unchanged
// ============================================================================
__global__ void __launch_bounds__(256, 2) kB()
{
    extern __shared__ char smc[];
    const uint32_t sbase = smem_u32(smc);

    const int t    = threadIdx.x;
    const int lane = t & 31;
    const int wid  = t >> 5;
    const int d    = blockIdx.z;
    const int i0   = blockIdx.x * 128;
    const int j0   = blockIdx.y * 128;

    const int m0 = (wid & 1) * 64;
    const int n0 = (wid >> 1) * 32;

    const __half* srcA = g_af + (size_t)d*NN + (size_t)i0*NSEQ;
    const __half* srcB = g_bf + (size_t)d*NN + (size_t)j0*NSEQ;

    auto issue = [&](int stage, int kc) {
        uint32_t sb = sbase + stage * 32768;
        #pragma unroll
        for (int q = 0; q < 4; q++) {
            int seg = t + 256*q;
            int row = seg >> 3;
            int s   = seg & 7;
            uint32_t off = SW128((uint32_t)(row*128 + s*16));
            CP_ASYNC16(sb + off,         srcA + (size_t)row*NSEQ + kc + s*8);
            CP_ASYNC16(sb + 16384 + off, srcB + (size_t)row*NSEQ + kc + s*8);
        }
        CP_COMMIT();
    };

    float acc[4][4][4];
    #pragma unroll
    for (int m = 0; m < 4; m++)
        #pragma unroll
        for (int n = 0; n < 4; n++)
            #pragma unroll
            for (int e = 0; e < 4; e++) acc[m][n][e] = 0.0f;

    const int aRow = lane & 15;
    const int aK   = (lane >> 4) * 16;
    const int bRow = (lane & 7) + ((lane >> 4) << 3);
    const int bK   = ((lane >> 3) & 1) * 16;

    issue(0, 0);

    for (int ch = 0; ch < 8; ch++) {
        const int stage = ch & 1;
        if (ch < 7) { issue(stage ^ 1, (ch + 1) * 64); CP_WAIT(1); }
        else        { CP_WAIT(0); }
        __syncthreads();

        const uint32_t sA = sbase + stage * 32768;
        const uint32_t sB = sA + 16384;

        #pragma unroll
        for (int kk = 0; kk < 4; kk++) {
            const uint32_t kOffA = (uint32_t)(kk*32) + aK;
            const uint32_t kOffB = (uint32_t)(kk*32) + bK;

            uint32_t bh[2][4];
            #pragma unroll
            for (int c = 0; c < 2; c++) {
                uint32_t off = (uint32_t)((n0 + c*16 + bRow) * 128) + kOffB;
                ldm4(sB + SW128(off), bh[c]);
            }
            uint32_t ah[4][4];
            #pragma unroll
            for (int f = 0; f < 4; f++) {
                uint32_t off = (uint32_t)((m0 + f*16 + aRow) * 128) + kOffA;
                ldm4(sA + SW128(off), ah[f]);
            }
            #pragma unroll
            for (int m = 0; m < 4; m++)
                #pragma unroll
                for (int n = 0; n < 4; n++)
                    mma16816(acc[m][n], ah[m], bh[n>>1][(n&1)*2], bh[n>>1][(n&1)*2+1]);
        }
        __syncthreads();
    }

    float* base = g_t + (size_t)d*NN;
    #pragma unroll
    for (int m = 0; m < 4; m++) {
        int r1 = i0 + m0 + m*16 + (lane >> 2);
        #pragma unroll
        for (int n = 0; n < 4; n++) {
            int c = j0 + n0 + n*8 + (lane & 3)*2;
            float2 lo = make_float2(acc[m][n][0], acc[m][n][1]);
            float2 hi = make_float2(acc[m][n][2], acc[m][n][3]);
            *(float2*)(base + (size_t)r1*NSEQ + c)       = lo;
            *(float2*)(base + (size_t)(r1+8)*NSEQ + c)   = hi;
        }
    }
}

// ============================================================================
// Kernel C (LN folded into epilogue) — unchanged from R12
// ============================================================================
__global__ void __launch_bounds__(256, 2) kC(
    const float* __restrict__ opb,
    float* __restrict__ out)
{
    extern __shared__ char smc[];
    const uint32_t sbase = smem_u32(smc);
    const uint32_t uTh  = sbase;
    const uint32_t uTl  = sbase + 16384;
    const uint32_t uWph = sbase + 32768;
    float* pS    = (float*)(smc + 65536);
    float* pQ    = (float*)(smc + 65536 + 4352);
    float* sMu   = (float*)(smc + 65536 + 8704);
    float* sRstd = (float*)(smc + 65536 + 8960);

    const int t    = threadIdx.x;
    const int lane = t & 31;
    const int wid  = t >> 5;
    const int r0   = blockIdx.x * 64;

    #pragma unroll
    for (int q = 0; q < 8; q++) {
        int seg = t + 256*q;
        int ch  = seg >> 4;
        int s8  = seg & 15;
        uint32_t dst = ((s8 >= 8) ? 16384u : 0u) + SW128((uint32_t)(ch*128 + (s8 & 7)*16));
        CP_ASYNC16(uWph + dst, g_oph + (size_t)ch*128 + s8*8);
    }
    CP_COMMIT();

    const int r4 = (t & 15) * 4;
    const int gg = t >> 4;
    float s0=0.f, s1=0.f, s2=0.f, s3=0.f;
    float q0=0.f, q1=0.f, q2=0.f, q3=0.f;
    #pragma unroll
    for (int q8 = 0; q8 < 8; q8++) {
        int dd = gg + 16*q8;
        float4 f = *(const float4*)(g_t + (size_t)dd*NN + r0 + r4);
        s0 += f.x; q0 += f.x*f.x;
        s1 += f.y; q1 += f.y*f.y;
        s2 += f.z; q2 += f.z*f.z;
        s3 += f.w; q3 += f.w*f.w;
        __half h0 = __float2half_rn(f.x), h1 = __float2half_rn(f.y);
        __half h2 = __float2half_rn(f.z), h3 = __float2half_rn(f.w);
        __half l0 = __float2half_rn(f.x - __half2float(h0));
        __half l1 = __float2half_rn(f.y - __half2float(h1));
        __half l2 = __float2half_rn(f.z - __half2float(h2));
        __half l3 = __float2half_rn(f.w - __half2float(h3));
        uint32_t off = SW128((uint32_t)(dd*128 + r4*2));
        __half2 hA = __halves2half2(h0, h1), hB = __halves2half2(h2, h3);
        __half2 lA = __halves2half2(l0, l1), lB = __halves2half2(l2, l3);
        *(__half2*)(smc + off)             = hA;
        *(__half2*)(smc + off + 4)         = hB;
        *(__half2*)(smc + 16384 + off)     = lA;
        *(__half2*)(smc + 16384 + off + 4) = lB;
    }
    pS[(r4+0)*17 + gg] = s0;  pQ[(r4+0)*17 + gg] = q0;
    pS[(r4+1)*17 + gg] = s1;  pQ[(r4+1)*17 + gg] = q1;
    pS[(r4+2)*17 + gg] = s2;  pQ[(r4+2)*17 + gg] = q2;
    pS[(r4+3)*17 + gg] = s3;  pQ[(r4+3)*17 + gg] = q3;
    __syncthreads();

    if (t < 64) {
        float s = 0.f, q = 0.f;
        #pragma unroll
        for (int g = 0; g < 16; g++) { s += pS[t*17 + g]; q += pQ[t*17 + g]; }
        float mu  = s * (1.0f/128.0f);
        float var = q * (1.0f/128.0f) - mu*mu;
        sMu[t]   = mu;
        sRstd[t] = rsqrtf(var + 1e-5f);
    }
    CP_WAIT(0);
    __syncthreads();

    const int bRow = (lane & 7) + ((lane >> 4) << 3);
    const int bK   = ((lane >> 3) & 1) * 16;
    const int m0   = (wid & 1) * 32;
    const int n0   = (wid >> 1) * 32;
    const int tD = (lane & 7) + ((lane & 16) >> 1);
    const int tR = ((lane >> 3) & 1) * 8;

    float acc[2][4][4];
    #pragma unroll
    for (int m = 0; m < 2; m++)
        #pragma unroll
        for (int n = 0; n < 4; n++)
            #pragma unroll
            for (int e = 0; e < 4; e++) acc[m][n][e] = 0.f;

    #pragma unroll
    for (int kk = 0; kk < 8; kk++) {
        const int d0 = kk * 16;
        const uint32_t halfW = (uint32_t)(kk >> 2) * 16384u;
        const uint32_t k32   = (uint32_t)(kk & 3) * 32u;

        uint32_t a2h[2][4], a2l[2][4];
        #pragma unroll
        for (int f = 0; f < 2; f++) {
            uint32_t off = SW128((uint32_t)((d0 + tD)*128 + (m0 + f*16 + tR)*2));
            ldm4t(uTh + off, a2h[f]);
            ldm4t(uTl + off, a2l[f]);
        }
        uint32_t ph[2][4];
        #pragma unroll
        for (int c = 0; c < 2; c++) {
            uint32_t off = SW128((uint32_t)((n0 + c*16 + bRow)*128) + k32 + bK);
            ldm4(uWph + halfW + off, ph[c]);
        }
        #pragma unroll
        for (int m = 0; m < 2; m++)
            #pragma unroll
            for (int n = 0; n < 4; n++) {
                int ci = n >> 1, bi = (n & 1) * 2;
                mma16816(acc[m][n], a2h[m], ph[ci][bi], ph[ci][bi+1]);
                mma16816(acc[m][n], a2l[m], ph[ci][bi], ph[ci][bi+1]);
            }
    }

    #pragma unroll
    for (int m = 0; m < 2; m++) {
        int row0 = m0 + m*16 + (lane >> 2);
        float mu0 = sMu[row0],   rs0 = sRstd[row0];
        float mu1 = sMu[row0+8], rs1 = sRstd[row0+8];
        #pragma unroll
        for (int n = 0; n < 4; n++) {
            int c0 = n0 + n*8 + (lane & 3)*2;
            float pb0 = __ldg(opb + c0),    pb1 = __ldg(opb + c0 + 1);
            float wb0 = __ldg(g_wbar + c0), wb1 = __ldg(g_wbar + c0 + 1);
            __half2 gv0 = *(const __half2*)(g_gate + (size_t)(r0 + row0)*DDIM + c0);
            __half2 gv1 = *(const __half2*)(g_gate + (size_t)(r0 + row0 + 8)*DDIM + c0);
            float2 g0 = __half22float2(gv0), g1 = __half22float2(gv1);
            float2 v0, v1;
            v0.x = g0.x * (rs0 * (acc[m][n][0] - mu0*wb0) + pb0);
            v0.y = g0.y * (rs0 * (acc[m][n][1] - mu0*wb1) + pb1);
            v1.x = g1.x * (rs1 * (acc[m][n][2] - mu1*wb0) + pb0);
            v1.y = g1.y * (rs1 * (acc[m][n][3] - mu1*wb1) + pb1);
            *(float2*)(out + (size_t)(r0 + row0)*DDIM + c0)     = v0;
            *(float2*)(out + (size_t)(r0 + row0 + 8)*DDIM + c0) = v1;
        }
    }
}

// ============================================================================
extern "C" void kernel_launch(void* const* d_in, const int* in_sizes, int n_in,
                              void* d_out, int out_size)
{
    const float* pair = (const float*)d_in[0];
    const float* mask = (const float*)d_in[1];
    const float* apw  = (const float*)d_in[2];
    const float* apb  = (const float*)d_in[3];
    const float* agw  = (const float*)d_in[4];
    const float* agb  = (const float*)d_in[5];
    const float* opw  = (const float*)d_in[6];
    const float* opb  = (const float*)d_in[7];
    const float* ogw  = (const float*)d_in[8];
    const float* ogb  = (const float*)d_in[9];
    float* out = (float*)d_out;

    const size_t smA = 98304 + 3584;   // ~99.5 KB -> 2 CTA/SM
    const size_t smB = 65536;
    const size_t smC = 75264;
    cudaFuncSetAttribute(kA, cudaFuncAttributeMaxDynamicSharedMemorySize, (int)smA);
    cudaFuncSetAttribute(kB, cudaFuncAttributeMaxDynamicSharedMemorySize, (int)smB);
    cudaFuncSetAttribute(kC, cudaFuncAttributeMaxDynamicSharedMemorySize, (int)smC);

    kW<<<128, 256>>>(agw, apw, ogw, opw);
    kWb<<<1, 256>>>(agw, apw, ogw, opw);
    kA<<<NN/128, 256, smA>>>(pair, mask, apb, agb, ogb);
    kB<<<dim3(4, 4, DDIM), 256, smB>>>();
    kC<<<NN/64, 256, smC>>>(opb, out);
}

// round 14
// speedup vs baseline: 1.0429x; 1.0429x over previous
#include <cuda_runtime.h>
#include <cuda_fp16.h>
#include <cstdint>
#include <cstddef>

#define NSEQ 512
#define DDIM 128
#define NN   (NSEQ*NSEQ)

// Scratch
static __device__ __half g_af[(size_t)DDIM * NN];
static __device__ __half g_bf[(size_t)DDIM * NN];
static __device__ float  g_t[(size_t)DDIM * NN];
static __device__ __half g_gate[(size_t)NN * DDIM];

// Pre-converted weights (fp16), row-major [ch][k]; column sums of the fp16 weights
static __device__ __half g_wg[256*128];
static __device__ __half g_wp[256*128];
static __device__ __half g_og[128*128];
static __device__ __half g_oph[128*128];
static __device__ float  g_wbar[128];
static __device__ float  g_wgbar[256];
static __device__ float  g_wpbar[256];
static __device__ float  g_ogbar[128];

__device__ __forceinline__ float sigmoidf_(float x) { return 1.0f / (1.0f + __expf(-x)); }

__device__ __forceinline__ uint32_t smem_u32(const void* p) {
    uint32_t a;
    asm("{ .reg .u64 t; cvta.to.shared.u64 t, %1; cvt.u32.u64 %0, t; }" : "=r"(a) : "l"(p));
    return a;
}
#define SW128(o) ((o) ^ (((o) >> 3) & 0x70))

#define CP_ASYNC16(dst, src) \
    asm volatile("cp.async.cg.shared.global [%0], [%1], 16;" :: "r"(dst), "l"(src) : "memory")
#define CP_COMMIT() asm volatile("cp.async.commit_group;" ::: "memory")
#define CP_WAIT(n)  asm volatile("cp.async.wait_group %0;" :: "n"(n) : "memory")

__device__ __forceinline__ void ldm4(uint32_t addr, uint32_t r[4]) {
    asm volatile("ldmatrix.sync.aligned.m8n8.x4.shared.b16 {%0,%1,%2,%3}, [%4];"
        : "=r"(r[0]), "=r"(r[1]), "=r"(r[2]), "=r"(r[3]) : "r"(addr));
}
__device__ __forceinline__ void ldm4t(uint32_t addr, uint32_t r[4]) {
    asm volatile("ldmatrix.sync.aligned.m8n8.x4.trans.shared.b16 {%0,%1,%2,%3}, [%4];"
        : "=r"(r[0]), "=r"(r[1]), "=r"(r[2]), "=r"(r[3]) : "r"(addr));
}
__device__ __forceinline__ void mma16816(float c[4], const uint32_t a[4],
                                         uint32_t b0, uint32_t b1) {
    asm volatile(
        "mma.sync.aligned.m16n8k16.row.col.f32.f16.f16.f32 "
        "{%0,%1,%2,%3}, {%4,%5,%6,%7}, {%8,%9}, {%0,%1,%2,%3};"
        : "+f"(c[0]), "+f"(c[1]), "+f"(c[2]), "+f"(c[3])
        : "r"(a[0]), "r"(a[1]), "r"(a[2]), "r"(a[3]), "r"(b0), "r"(b1));
}

// ============================================================================
__global__ void __launch_bounds__(256) kW(
    const float* __restrict__ agw, const float* __restrict__ apw,
    const float* __restrict__ ogw, const float* __restrict__ opw)
{
    int i = blockIdx.x * 256 + threadIdx.x;
    if (i < 256*128) {
        g_wg[i] = __float2half_rn(agw[i]);
        g_wp[i] = __float2half_rn(apw[i]);
    }
    if (i < 128*128) {
        g_og[i]  = __float2half_rn(ogw[i]);
        g_oph[i] = __float2half_rn(opw[i]);
    }
}
__global__ void kWb(const float* __restrict__ agw, const float* __restrict__ apw,
                    const float* __restrict__ ogw, const float* __restrict__ opw)
{
    int c = threadIdx.x;
    float sg = 0.f, sp = 0.f;
    for (int d = 0; d < 128; d++) {
        sg += __half2float(__float2half_rn(agw[c*128 + d]));
        sp += __half2float(__float2half_rn(apw[c*128 + d]));
    }
    g_wgbar[c] = sg;
    g_wpbar[c] = sp;
    if (c < 128) {
        float so = 0.f, sw = 0.f;
        for (int d = 0; d < 128; d++) {
            so += __half2float(__float2half_rn(ogw[c*128 + d]));
            sw += __half2float(__float2half_rn(opw[c*128 + d]));
        }
        g_ogbar[c] = so;
        g_wbar[c]  = sw;
    }
}

// ============================================================================
// Kernel A (LN folded into epilogue; coalesced prologue)
// smem: A 32K @0 | W 2x32K @32768 | pS/pQ [128][9] @98304 | mu/rstd/mask
// ============================================================================
__global__ void __launch_bounds__(256, 2) kA(
    const float* __restrict__ pair, const float* __restrict__ mask,
    const float* __restrict__ apb, const float* __restrict__ agb,
    const float* __restrict__ ogb)
{
    extern __shared__ char smc[];
    const uint32_t sbase = smem_u32(smc);
    const uint32_t uA = sbase;
    const uint32_t uW = sbase + 32768;
    float* pS    = (float*)(smc + 98304);               // [128][9]
    float* pQ    = (float*)(smc + 98304 + 4608);        // [128][9]
    float* sMu   = (float*)(smc + 98304 + 9216);        // [128]
    float* sRstd = (float*)(smc + 98304 + 9728);        // [128]
    float* sM    = (float*)(smc + 98304 + 10240);       // [128]

    const int t    = threadIdx.x;
    const int lane = t & 31;
    const int wid  = t >> 5;
    const int r0   = blockIdx.x * 128;

    auto prefetchW = [&](int stage, int c) {
        uint32_t sb = uW + stage * 32768;
        const __half* w0;
        const __half* w1 = nullptr;
        if (c < 4) { w0 = g_wg + (size_t)c*64*128; w1 = g_wp + (size_t)c*64*128; }
        else       { w0 = g_og + (size_t)(c - 4)*64*128; }
        #pragma unroll
        for (int q = 0; q < 4; q++) {
            int seg = t + 256*q;
            int ch  = seg >> 4;
            int s8  = seg & 15;
            uint32_t dst = ((s8 >= 8) ? 8192u : 0u) + SW128((uint32_t)(ch*128 + (s8 & 7)*16));
            CP_ASYNC16(sb + dst, w0 + (size_t)ch*128 + s8*8);
            if (w1) CP_ASYNC16(sb + 16384 + dst, w1 + (size_t)ch*128 + s8*8);
        }
        CP_COMMIT();
    };
    prefetchW(0, 0);

    if (t < 128) sM[t] = mask[r0 + t];

    // coalesced raw-pair load: 8 threads/row, 16 floats each; partial stats
    #pragma unroll
    for (int q8 = 0; q8 < 4; q8++) {
        int seg = t + 256*q8;            // 0..1023
        int row = seg >> 3;              // 0..127
        int s   = seg & 7;               // 16-float group
        const float* src = pair + (size_t)(r0 + row)*DDIM + s*16;
        float sa = 0.f, qa = 0.f;
        uint32_t hbuf[8];
        #pragma unroll
        for (int i = 0; i < 4; i++) {
            float4 f = *(const float4*)(src + i*4);
            sa += (f.x + f.y) + (f.z + f.w);
            qa += (f.x*f.x + f.y*f.y) + (f.z*f.z + f.w*f.w);
            __half2 hA = __halves2half2(__float2half_rn(f.x), __float2half_rn(f.y));
            __half2 hB = __halves2half2(__float2half_rn(f.z), __float2half_rn(f.w));
            hbuf[i*2]   = *(uint32_t*)&hA;
            hbuf[i*2+1] = *(uint32_t*)&hB;
        }
        uint32_t base = (s >= 4) ? 16384u : 0u;
        uint32_t bo   = (uint32_t)(row*128 + (s & 3)*32);
        *(uint4*)(smc + base + SW128(bo))      = make_uint4(hbuf[0], hbuf[1], hbuf[2], hbuf[3]);
        *(uint4*)(smc + base + SW128(bo + 16)) = make_uint4(hbuf[4], hbuf[5], hbuf[6], hbuf[7]);
        pS[row*9 + s] = sa;
        pQ[row*9 + s] = qa;
    }
    __syncthreads();
    if (t < 128) {
        float ss = 0.f, q2 = 0.f;
        #pragma unroll
        for (int g = 0; g < 8; g++) { ss += pS[t*9 + g]; q2 += pQ[t*9 + g]; }
        float mu  = ss * (1.0f/128.0f);
        float var = q2 * (1.0f/128.0f) - mu*mu;
        sMu[t]   = mu;
        sRstd[t] = rsqrtf(var + 1e-5f);
    }

    const int aRow = lane & 15;
    const int aK   = (lane >> 4) * 16;
    const int bRow = (lane & 7) + ((lane >> 4) << 3);
    const int bK   = ((lane >> 3) & 1) * 16;
    const int m0   = (wid & 1) * 64;
    const int n0   = (wid >> 1) * 16;

    for (int c = 0; c < 6; c++) {
        const int stage = c & 1;
        if (c < 5) { prefetchW(stage ^ 1, c + 1); CP_WAIT(1); }
        else       { CP_WAIT(0); }
        __syncthreads();

        const uint32_t sW0 = uW + stage * 32768;
        const uint32_t sW1 = sW0 + 16384;
        const bool isAB = (c < 4);
        const int ch0   = isAB ? c * 64 : (c - 4) * 64;

        if (isAB) {
            float accg[4][2][4], accp[4][2][4];
            #pragma unroll
            for (int m = 0; m < 4; m++)
                #pragma unroll
                for (int n = 0; n < 2; n++)
                    #pragma unroll
                    for (int e = 0; e < 4; e++) { accg[m][n][e] = 0.f; accp[m][n][e] = 0.f; }

            #pragma unroll
            for (int kk = 0; kk < 8; kk++) {
                const uint32_t halfA = (uint32_t)(kk >> 2) * 16384u;
                const uint32_t halfW = (uint32_t)(kk >> 2) * 8192u;
                const uint32_t k32   = (uint32_t)(kk & 3) * 32u;

                uint32_t ah[4][4];
                #pragma unroll
                for (int f = 0; f < 4; f++) {
                    uint32_t off = SW128((uint32_t)((m0 + f*16 + aRow)*128) + k32 + aK);
                    ldm4(uA + halfA + off, ah[f]);
                }
                uint32_t gh[4], ph[4];
                {
                    uint32_t off = SW128((uint32_t)((n0 + bRow)*128) + k32 + bK);
                    ldm4(sW0 + halfW + off, gh);
                    ldm4(sW1 + halfW + off, ph);
                }
                #pragma unroll
                for (int m = 0; m < 4; m++)
                    #pragma unroll
                    for (int n = 0; n < 2; n++) {
                        mma16816(accg[m][n], ah[m], gh[n*2], gh[n*2+1]);
                        mma16816(accp[m][n], ah[m], ph[n*2], ph[n*2+1]);
                    }
            }

            __half* dst = (ch0 < 128) ? (g_af + (size_t)ch0 * NN)
                                      : (g_bf + (size_t)(ch0 - 128) * NN);
            #pragma unroll
            for (int m = 0; m < 4; m++) {
                int row0 = m0 + m*16 + (lane >> 2);
                float mu0 = sMu[row0],   rs0 = sRstd[row0];
                float mu1 = sMu[row0+8], rs1 = sRstd[row0+8];
                float mv0 = sM[row0],    mv1 = sM[row0 + 8];
                #pragma unroll
                for (int n = 0; n < 2; n++) {
                    int c0 = n0 + n*8 + (lane & 3)*2;
                    float gb0 = __ldg(agb + ch0 + c0),   gb1 = __ldg(agb + ch0 + c0 + 1);
                    float pb0 = __ldg(apb + ch0 + c0),   pb1 = __ldg(apb + ch0 + c0 + 1);
                    float wg0 = __ldg(g_wgbar + ch0 + c0), wg1 = __ldg(g_wgbar + ch0 + c0 + 1);
                    float wp0 = __ldg(g_wpbar + ch0 + c0), wp1 = __ldg(g_wpbar + ch0 + c0 + 1);
                    float v00 = mv0 * sigmoidf_(rs0*(accg[m][n][0] - mu0*wg0) + gb0)
                                    * (rs0*(accp[m][n][0] - mu0*wp0) + pb0);
                    float v01 = mv0 * sigmoidf_(rs0*(accg[m][n][1] - mu0*wg1) + gb1)
                                    * (rs0*(accp[m][n][1] - mu0*wp1) + pb1);
                    float v10 = mv1 * sigmoidf_(rs1*(accg[m][n][2] - mu1*wg0) + gb0)
                                    * (rs1*(accp[m][n][2] - mu1*wp0) + pb0);
                    float v11 = mv1 * sigmoidf_(rs1*(accg[m][n][3] - mu1*wg1) + gb1)
                                    * (rs1*(accp[m][n][3] - mu1*wp1) + pb1);
                    __half* p0 = dst + (size_t)c0 * NN + r0 + row0;
                    __half* p1 = dst + (size_t)(c0 + 1) * NN + r0 + row0;
                    p0[0] = __float2half_rn(v00);
                    p1[0] = __float2half_rn(v01);
                    p0[8] = __float2half_rn(v10);
                    p1[8] = __float2half_rn(v11);
                }
            }
        } else {
            float accg[4][2][4];
            #pragma unroll
            for (int m = 0; m < 4; m++)
                #pragma unroll
                for (int n = 0; n < 2; n++)
                    #pragma unroll
                    for (int e = 0; e < 4; e++) accg[m][n][e] = 0.f;

            #pragma unroll
            for (int kk = 0; kk < 8; kk++) {
                const uint32_t halfA = (uint32_t)(kk >> 2) * 16384u;
                const uint32_t halfW = (uint32_t)(kk >> 2) * 8192u;
                const uint32_t k32   = (uint32_t)(kk & 3) * 32u;

                uint32_t ah[4][4];
                #pragma unroll
                for (int f = 0; f < 4; f++) {
                    uint32_t off = SW128((uint32_t)((m0 + f*16 + aRow)*128) + k32 + aK);
                    ldm4(uA + halfA + off, ah[f]);
                }
                uint32_t gh[4];
                {
                    uint32_t off = SW128((uint32_t)((n0 + bRow)*128) + k32 + bK);
                    ldm4(sW0 + halfW + off, gh);
                }
                #pragma unroll
                for (int m = 0; m < 4; m++)
                    #pragma unroll
                    for (int n = 0; n < 2; n++)
                        mma16816(accg[m][n], ah[m], gh[n*2], gh[n*2+1]);
            }

            #pragma unroll
            for (int m = 0; m < 4; m++) {
                int row0 = m0 + m*16 + (lane >> 2);
                float mu0 = sMu[row0],   rs0 = sRstd[row0];
                float mu1 = sMu[row0+8], rs1 = sRstd[row0+8];
                #pragma unroll
                for (int n = 0; n < 2; n++) {
                    int c0 = n0 + n*8 + (lane & 3)*2;
                    float gb0 = __ldg(ogb + ch0 + c0),     gb1 = __ldg(ogb + ch0 + c0 + 1);
                    float wo0 = __ldg(g_ogbar + ch0 + c0), wo1 = __ldg(g_ogbar + ch0 + c0 + 1);
                    __half2 h0 = __halves2half2(
                        __float2half_rn(sigmoidf_(rs0*(accg[m][n][0] - mu0*wo0) + gb0)),
                        __float2half_rn(sigmoidf_(rs0*(accg[m][n][1] - mu0*wo1) + gb1)));
                    __half2 h1 = __halves2half2(
                        __float2half_rn(sigmoidf_(rs1*(accg[m][n][2] - mu1*wo0) + gb0)),
                        __float2half_rn(sigmoidf_(rs1*(accg[m][n][3] - mu1*wo1) + gb1)));
                    *(__half2*)(g_gate + (size_t)(r0 + row0)*DDIM + ch0 + c0)     = h0;
                    *(__half2*)(g_gate + (size_t)(r0 + row0 + 8)*DDIM + ch0 + c0) = h1;
                }
            }
        }
        __syncthreads();
    }
}

// ============================================================================
// Kernel B (fp16 1-term) — unchanged
// ============================================================================
__global__ void __launch_bounds__(256, 2) kB()
{
    extern __shared__ char smc[];
    const uint32_t sbase = smem_u32(smc);

    const int t    = threadIdx.x;
    const int lane = t & 31;
    const int wid  = t >> 5;
    const int d    = blockIdx.z;
    const int i0   = blockIdx.x * 128;
    const int j0   = blockIdx.y * 128;

    const int m0 = (wid & 1) * 64;
    const int n0 = (wid >> 1) * 32;

    const __half* srcA = g_af + (size_t)d*NN + (size_t)i0*NSEQ;
    const __half* srcB = g_bf + (size_t)d*NN + (size_t)j0*NSEQ;

    auto issue = [&](int stage, int kc) {
        uint32_t sb = sbase + stage * 32768;
        #pragma unroll
        for (int q = 0; q < 4; q++) {
            int seg = t + 256*q;
            int row = seg >> 3;
            int s   = seg & 7;
            uint32_t off = SW128((uint32_t)(row*128 + s*16));
            CP_ASYNC16(sb + off,         srcA + (size_t)row*NSEQ + kc + s*8);
            CP_ASYNC16(sb + 16384 + off, srcB + (size_t)row*NSEQ + kc + s*8);
        }
        CP_COMMIT();
    };

    float acc[4][4][4];
    #pragma unroll
    for (int m = 0; m < 4; m++)
        #pragma unroll
        for (int n = 0; n < 4; n++)
            #pragma unroll
            for (int e = 0; e < 4; e++) acc[m][n][e] = 0.0f;

    const int aRow = lane & 15;
    const int aK   = (lane >> 4) * 16;
    const int bRow = (lane & 7) + ((lane >> 4) << 3);
    const int bK   = ((lane >> 3) & 1) * 16;

    issue(0, 0);

    for (int ch = 0; ch < 8; ch++) {
        const int stage = ch & 1;
        if (ch < 7) { issue(stage ^ 1, (ch + 1) * 64); CP_WAIT(1); }
        else        { CP_WAIT(0); }
        __syncthreads();

        const uint32_t sA = sbase + stage * 32768;
        const uint32_t sB = sA + 16384;

        #pragma unroll
        for (int kk = 0; kk < 4; kk++) {
            const uint32_t kOffA = (uint32_t)(kk*32) + aK;
            const uint32_t kOffB = (uint32_t)(kk*32) + bK;

            uint32_t bh[2][4];
            #pragma unroll
            for (int c = 0; c < 2; c++) {
                uint32_t off = (uint32_t)((n0 + c*16 + bRow) * 128) + kOffB;
                ldm4(sB + SW128(off), bh[c]);
            }
            uint32_t ah[4][4];
            #pragma unroll
            for (int f = 0; f < 4; f++) {
                uint32_t off = (uint32_t)((m0 + f*16 + aRow) * 128) + kOffA;
                ldm4(sA + SW128(off), ah[f]);
            }
            #pragma unroll
            for (int m = 0; m < 4; m++)
                #pragma unroll
                for (int n = 0; n < 4; n++)
                    mma16816(acc[m][n], ah[m], bh[n>>1][(n&1)*2], bh[n>>1][(n&1)*2+1]);
        }
        __syncthreads();
    }

    float* base = g_t + (size_t)d*NN;
    #pragma unroll
    for (int m = 0; m < 4; m++) {
        int r1 = i0 + m0 + m*16 + (lane >> 2);
        #pragma unroll
        for (int n = 0; n < 4; n++) {
            int c = j0 + n0 + n*8 + (lane & 3)*2;
            float2 lo = make_float2(acc[m][n][0], acc[m][n][1]);
            float2 hi = make_float2(acc[m][n][2], acc[m][n][3]);
            *(float2*)(base + (size_t)r1*NSEQ + c)       = lo;
            *(float2*)(base + (size_t)(r1+8)*NSEQ + c)   = hi;
        }
    }
}

// ============================================================================
// Kernel C (LN folded into epilogue) — unchanged
// ============================================================================
__global__ void __launch_bounds__(256, 2) kC(
    const float* __restrict__ opb,
    float* __restrict__ out)
{
    extern __shared__ char smc[];
    const uint32_t sbase = smem_u32(smc);
    const uint32_t uTh  = sbase;
    const uint32_t uTl  = sbase + 16384;
    const uint32_t uWph = sbase + 32768;
    float* pS    = (float*)(smc + 65536);
    float* pQ    = (float*)(smc + 65536 + 4352);
    float* sMu   = (float*)(smc + 65536 + 8704);
    float* sRstd = (float*)(smc + 65536 + 8960);

    const int t    = threadIdx.x;
    const int lane = t & 31;
    const int wid  = t >> 5;
    const int r0   = blockIdx.x * 64;

    #pragma unroll
    for (int q = 0; q < 8; q++) {
        int seg = t + 256*q;
        int ch  = seg >> 4;
        int s8  = seg & 15;
        uint32_t dst = ((s8 >= 8) ? 16384u : 0u) + SW128((uint32_t)(ch*128 + (s8 & 7)*16));
        CP_ASYNC16(uWph + dst, g_oph + (size_t)ch*128 + s8*8);
    }
    CP_COMMIT();

    const int r4 = (t & 15) * 4;
    const int gg = t >> 4;
    float s0=0.f, s1=0.f, s2=0.f, s3=0.f;
    float q0=0.f, q1=0.f, q2=0.f, q3=0.f;
    #pragma unroll
    for (int q8 = 0; q8 < 8; q8++) {
        int dd = gg + 16*q8;
        float4 f = *(const float4*)(g_t + (size_t)dd*NN + r0 + r4);
        s0 += f.x; q0 += f.x*f.x;
        s1 += f.y; q1 += f.y*f.y;
        s2 += f.z; q2 += f.z*f.z;
        s3 += f.w; q3 += f.w*f.w;
        __half h0 = __float2half_rn(f.x), h1 = __float2half_rn(f.y);
        __half h2 = __float2half_rn(f.z), h3 = __float2half_rn(f.w);
        __half l0 = __float2half_rn(f.x - __half2float(h0));
        __half l1 = __float2half_rn(f.y - __half2float(h1));
        __half l2 = __float2half_rn(f.z - __half2float(h2));
        __half l3 = __float2half_rn(f.w - __half2float(h3));
        uint32_t off = SW128((uint32_t)(dd*128 + r4*2));
        __half2 hA = __halves2half2(h0, h1), hB = __halves2half2(h2, h3);
        __half2 lA = __halves2half2(l0, l1), lB = __halves2half2(l2, l3);
        *(__half2*)(smc + off)             = hA;
        *(__half2*)(smc + off + 4)         = hB;
        *(__half2*)(smc + 16384 + off)     = lA;
        *(__half2*)(smc + 16384 + off + 4) = lB;
    }
    pS[(r4+0)*17 + gg] = s0;  pQ[(r4+0)*17 + gg] = q0;
    pS[(r4+1)*17 + gg] = s1;  pQ[(r4+1)*17 + gg] = q1;
    pS[(r4+2)*17 + gg] = s2;  pQ[(r4+2)*17 + gg] = q2;
    pS[(r4+3)*17 + gg] = s3;  pQ[(r4+3)*17 + gg] = q3;
    __syncthreads();

    if (t < 64) {
        float s = 0.f, q = 0.f;
        #pragma unroll
        for (int g = 0; g < 16; g++) { s += pS[t*17 + g]; q += pQ[t*17 + g]; }
        float mu  = s * (1.0f/128.0f);
        float var = q * (1.0f/128.0f) - mu*mu;
        sMu[t]   = mu;
        sRstd[t] = rsqrtf(var + 1e-5f);
    }
    CP_WAIT(0);
    __syncthreads();

    const int bRow = (lane & 7) + ((lane >> 4) << 3);
    const int bK   = ((lane >> 3) & 1) * 16;
    const int m0   = (wid & 1) * 32;
    const int n0   = (wid >> 1) * 32;
    const int tD = (lane & 7) + ((lane & 16) >> 1);
    const int tR = ((lane >> 3) & 1) * 8;

    float acc[2][4][4];
    #pragma unroll
    for (int m = 0; m < 2; m++)
        #pragma unroll
        for (int n = 0; n < 4; n++)
            #pragma unroll
            for (int e = 0; e < 4; e++) acc[m][n][e] = 0.f;

    #pragma unroll
    for (int kk = 0; kk < 8; kk++) {
        const int d0 = kk * 16;
        const uint32_t halfW = (uint32_t)(kk >> 2) * 16384u;
        const uint32_t k32   = (uint32_t)(kk & 3) * 32u;

        uint32_t a2h[2][4], a2l[2][4];
        #pragma unroll
        for (int f = 0; f < 2; f++) {
            uint32_t off = SW128((uint32_t)((d0 + tD)*128 + (m0 + f*16 + tR)*2));
            ldm4t(uTh + off, a2h[f]);
            ldm4t(uTl + off, a2l[f]);
        }
        uint32_t ph[2][4];
        #pragma unroll
        for (int c = 0; c < 2; c++) {
            uint32_t off = SW128((uint32_t)((n0 + c*16 + bRow)*128) + k32 + bK);
            ldm4(uWph + halfW + off, ph[c]);
        }
        #pragma unroll
        for (int m = 0; m < 2; m++)
            #pragma unroll
            for (int n = 0; n < 4; n++) {
                int ci = n >> 1, bi = (n & 1) * 2;
                mma16816(acc[m][n], a2h[m], ph[ci][bi], ph[ci][bi+1]);
                mma16816(acc[m][n], a2l[m], ph[ci][bi], ph[ci][bi+1]);
            }
    }

    #pragma unroll
    for (int m = 0; m < 2; m++) {
        int row0 = m0 + m*16 + (lane >> 2);
        float mu0 = sMu[row0],   rs0 = sRstd[row0];
        float mu1 = sMu[row0+8], rs1 = sRstd[row0+8];
        #pragma unroll
        for (int n = 0; n < 4; n++) {
            int c0 = n0 + n*8 + (lane & 3)*2;
            float pb0 = __ldg(opb + c0),    pb1 = __ldg(opb + c0 + 1);
            float wb0 = __ldg(g_wbar + c0), wb1 = __ldg(g_wbar + c0 + 1);
            __half2 gv0 = *(const __half2*)(g_gate + (size_t)(r0 + row0)*DDIM + c0);
            __half2 gv1 = *(const __half2*)(g_gate + (size_t)(r0 + row0 + 8)*DDIM + c0);
            float2 g0 = __half22float2(gv0), g1 = __half22float2(gv1);
            float2 v0, v1;
            v0.x = g0.x * (rs0 * (acc[m][n][0] - mu0*wb0) + pb0);
            v0.y = g0.y * (rs0 * (acc[m][n][1] - mu0*wb1) + pb1);
            v1.x = g1.x * (rs1 * (acc[m][n][2] - mu1*wb0) + pb0);
            v1.y = g1.y * (rs1 * (acc[m][n][3] - mu1*wb1) + pb1);
            *(float2*)(out + (size_t)(r0 + row0)*DDIM + c0)     = v0;
            *(float2*)(out + (size_t)(r0 + row0 + 8)*DDIM + c0) = v1;
        }
    }
}

// ============================================================================
extern "C" void kernel_launch(void* const* d_in, const int* in_sizes, int n_in,
                              void* d_out, int out_size)
{
    const float* pair = (const float*)d_in[0];
    const float* mask = (const float*)d_in[1];
    const float* apw  = (const float*)d_in[2];
    const float* apb  = (const float*)d_in[3];
    const float* agw  = (const float*)d_in[4];
    const float* agb  = (const float*)d_in[5];
    const float* opw  = (const float*)d_in[6];
    const float* opb  = (const float*)d_in[7];
    const float* ogw  = (const float*)d_in[8];
    const float* ogb  = (const float*)d_in[9];
    float* out = (float*)d_out;

    const size_t smA = 98304 + 10752;   // ~106.5 KB -> 2 CTA/SM
    const size_t smB = 65536;
    const size_t smC = 75264;
    cudaFuncSetAttribute(kA, cudaFuncAttributeMaxDynamicSharedMemorySize, (int)smA);
    cudaFuncSetAttribute(kB, cudaFuncAttributeMaxDynamicSharedMemorySize, (int)smB);
    cudaFuncSetAttribute(kC, cudaFuncAttributeMaxDynamicSharedMemorySize, (int)smC);

    kW<<<128, 256>>>(agw, apw, ogw, opw);
    kWb<<<1, 256>>>(agw, apw, ogw, opw);
    kA<<<NN/128, 256, smA>>>(pair, mask, apb, agb, ogb);
    kB<<<dim3(4, 4, DDIM), 256, smB>>>();
    kC<<<NN/64, 256, smC>>>(opb, out);
}

// round 15
// speedup vs baseline: 1.0720x; 1.0279x over previous
#include <cuda_runtime.h>
#include <cuda_fp16.h>
#include <cstdint>
#include <cstddef>

#define NSEQ 512
#define DDIM 128
#define NN   (NSEQ*NSEQ)

// Scratch
static __device__ __half g_af[(size_t)DDIM * NN];
static __device__ __half g_bf[(size_t)DDIM * NN];
static __device__ float  g_t[(size_t)DDIM * NN];
static __device__ __half g_gate[(size_t)NN * DDIM];

// Pre-converted weights (fp16), row-major [ch][k]
static __device__ __half g_wg[256*128];
static __device__ __half g_wp[256*128];
static __device__ __half g_og[128*128];
static __device__ __half g_oph[128*128];
static __device__ float  g_wbar[128];     // sums of fp16(opw)

__device__ __forceinline__ float sigmoidf_(float x) { return 1.0f / (1.0f + __expf(-x)); }

__device__ __forceinline__ uint32_t smem_u32(const void* p) {
    uint32_t a;
    asm("{ .reg .u64 t; cvta.to.shared.u64 t, %1; cvt.u32.u64 %0, t; }" : "=r"(a) : "l"(p));
    return a;
}
#define SW128(o) ((o) ^ (((o) >> 3) & 0x70))

#define CP_ASYNC16(dst, src) \
    asm volatile("cp.async.cg.shared.global [%0], [%1], 16;" :: "r"(dst), "l"(src) : "memory")
#define CP_COMMIT() asm volatile("cp.async.commit_group;" ::: "memory")
#define CP_WAIT(n)  asm volatile("cp.async.wait_group %0;" :: "n"(n) : "memory")

__device__ __forceinline__ void ldm4(uint32_t addr, uint32_t r[4]) {
    asm volatile("ldmatrix.sync.aligned.m8n8.x4.shared.b16 {%0,%1,%2,%3}, [%4];"
        : "=r"(r[0]), "=r"(r[1]), "=r"(r[2]), "=r"(r[3]) : "r"(addr));
}
__device__ __forceinline__ void ldm4t(uint32_t addr, uint32_t r[4]) {
    asm volatile("ldmatrix.sync.aligned.m8n8.x4.trans.shared.b16 {%0,%1,%2,%3}, [%4];"
        : "=r"(r[0]), "=r"(r[1]), "=r"(r[2]), "=r"(r[3]) : "r"(addr));
}
__device__ __forceinline__ void mma16816(float c[4], const uint32_t a[4],
                                         uint32_t b0, uint32_t b1) {
    asm volatile(
        "mma.sync.aligned.m16n8k16.row.col.f32.f16.f16.f32 "
        "{%0,%1,%2,%3}, {%4,%5,%6,%7}, {%8,%9}, {%0,%1,%2,%3};"
        : "+f"(c[0]), "+f"(c[1]), "+f"(c[2]), "+f"(c[3])
        : "r"(a[0]), "r"(a[1]), "r"(a[2]), "r"(a[3]), "r"(b0), "r"(b1));
}

// ============================================================================
__global__ void __launch_bounds__(256) kW(
    const float* __restrict__ agw, const float* __restrict__ apw,
    const float* __restrict__ ogw, const float* __restrict__ opw)
{
    int i = blockIdx.x * 256 + threadIdx.x;
    if (i < 256*128) {
        g_wg[i] = __float2half_rn(agw[i]);
        g_wp[i] = __float2half_rn(apw[i]);
    }
    if (i < 128*128) {
        g_og[i]  = __float2half_rn(ogw[i]);
        g_oph[i] = __float2half_rn(opw[i]);
    }
}
__global__ void kWb(const float* __restrict__ opw) {
    int c = threadIdx.x;
    float s = 0.f;
    for (int d = 0; d < 128; d++) s += __half2float(__float2half_rn(opw[c*128 + d]));
    g_wbar[c] = s;
}

// ============================================================================
// Kernel A — R12 version (LN shuffle prologue, W pipelined, direct stores)
// smem: A 32K @0 | W 2x32K @32768 | stats/mask @98304
// ============================================================================
__global__ void __launch_bounds__(256, 2) kA(
    const float* __restrict__ pair, const float* __restrict__ mask,
    const float* __restrict__ apb, const float* __restrict__ agb,
    const float* __restrict__ ogb)
{
    extern __shared__ char smc[];
    const uint32_t sbase = smem_u32(smc);
    const uint32_t uA = sbase;
    const uint32_t uW = sbase + 32768;
    float* sM = (float*)(smc + 98304);

    const int t    = threadIdx.x;
    const int lane = t & 31;
    const int wid  = t >> 5;
    const int r0   = blockIdx.x * 128;

    auto prefetchW = [&](int stage, int c) {
        uint32_t sb = uW + stage * 32768;
        const __half* w0;
        const __half* w1 = nullptr;
        if (c < 4) { w0 = g_wg + (size_t)c*64*128; w1 = g_wp + (size_t)c*64*128; }
        else       { w0 = g_og + (size_t)(c - 4)*64*128; }
        #pragma unroll
        for (int q = 0; q < 4; q++) {
            int seg = t + 256*q;
            int ch  = seg >> 4;
            int s8  = seg & 15;
            uint32_t dst = ((s8 >= 8) ? 8192u : 0u) + SW128((uint32_t)(ch*128 + (s8 & 7)*16));
            CP_ASYNC16(sb + dst, w0 + (size_t)ch*128 + s8*8);
            if (w1) CP_ASYNC16(sb + 16384 + dst, w1 + (size_t)ch*128 + s8*8);
        }
        CP_COMMIT();
    };
    prefetchW(0, 0);

    if (t < 128) sM[t] = mask[r0 + t];

    // LN(pair) -> fp16 A tiles
    for (int row = wid; row < 128; row += 8) {
        const float* src = pair + (size_t)(r0 + row) * DDIM;
        float x[4] = { src[lane], src[lane+32], src[lane+64], src[lane+96] };
        float s = x[0] + x[1] + x[2] + x[3];
        #pragma unroll
        for (int o = 16; o > 0; o >>= 1) s += __shfl_xor_sync(0xffffffffu, s, o);
        float mu = s * (1.0f/128.0f);
        float d0 = x[0]-mu, d1 = x[1]-mu, d2 = x[2]-mu, d3 = x[3]-mu;
        float v = d0*d0 + d1*d1 + d2*d2 + d3*d3;
        #pragma unroll
        for (int o = 16; o > 0; o >>= 1) v += __shfl_xor_sync(0xffffffffu, v, o);
        float rstd = rsqrtf(v * (1.0f/128.0f) + 1e-5f);
        float dd[4] = { d0*rstd, d1*rstd, d2*rstd, d3*rstd };
        #pragma unroll
        for (int j = 0; j < 4; j++) {
            uint32_t off = (uint32_t)(j >= 2) * 16384u
                         + SW128((uint32_t)(row*128 + (lane + 32*(j&1))*2));
            *(__half*)(smc + off) = __float2half_rn(dd[j]);
        }
    }

    const int aRow = lane & 15;
    const int aK   = (lane >> 4) * 16;
    const int bRow = (lane & 7) + ((lane >> 4) << 3);
    const int bK   = ((lane >> 3) & 1) * 16;
    const int m0   = (wid & 1) * 64;
    const int n0   = (wid >> 1) * 16;

    for (int c = 0; c < 6; c++) {
        const int stage = c & 1;
        if (c < 5) { prefetchW(stage ^ 1, c + 1); CP_WAIT(1); }
        else       { CP_WAIT(0); }
        __syncthreads();

        const uint32_t sW0 = uW + stage * 32768;
        const uint32_t sW1 = sW0 + 16384;
        const bool isAB = (c < 4);
        const int ch0   = isAB ? c * 64 : (c - 4) * 64;

        if (isAB) {
            float accg[4][2][4], accp[4][2][4];
            #pragma unroll
            for (int m = 0; m < 4; m++)
                #pragma unroll
                for (int n = 0; n < 2; n++)
                    #pragma unroll
                    for (int e = 0; e < 4; e++) { accg[m][n][e] = 0.f; accp[m][n][e] = 0.f; }

            #pragma unroll
            for (int kk = 0; kk < 8; kk++) {
                const uint32_t halfA = (uint32_t)(kk >> 2) * 16384u;
                const uint32_t halfW = (uint32_t)(kk >> 2) * 8192u;
                const uint32_t k32   = (uint32_t)(kk & 3) * 32u;

                uint32_t ah[4][4];
                #pragma unroll
                for (int f = 0; f < 4; f++) {
                    uint32_t off = SW128((uint32_t)((m0 + f*16 + aRow)*128) + k32 + aK);
                    ldm4(uA + halfA + off, ah[f]);
                }
                uint32_t gh[4], ph[4];
                {
                    uint32_t off = SW128((uint32_t)((n0 + bRow)*128) + k32 + bK);
                    ldm4(sW0 + halfW + off, gh);
                    ldm4(sW1 + halfW + off, ph);
                }
                #pragma unroll
                for (int m = 0; m < 4; m++)
                    #pragma unroll
                    for (int n = 0; n < 2; n++) {
                        mma16816(accg[m][n], ah[m], gh[n*2], gh[n*2+1]);
                        mma16816(accp[m][n], ah[m], ph[n*2], ph[n*2+1]);
                    }
            }

            __half* dst = (ch0 < 128) ? (g_af + (size_t)ch0 * NN)
                                      : (g_bf + (size_t)(ch0 - 128) * NN);
            #pragma unroll
            for (int m = 0; m < 4; m++) {
                int row0 = m0 + m*16 + (lane >> 2);
                #pragma unroll
                for (int n = 0; n < 2; n++) {
                    int c0 = n0 + n*8 + (lane & 3)*2;
                    float gb0 = __ldg(agb + ch0 + c0), gb1 = __ldg(agb + ch0 + c0 + 1);
                    float pb0 = __ldg(apb + ch0 + c0), pb1 = __ldg(apb + ch0 + c0 + 1);
                    float mv0 = sM[row0], mv1 = sM[row0 + 8];
                    float v00 = mv0 * sigmoidf_(accg[m][n][0] + gb0) * (accp[m][n][0] + pb0);
                    float v01 = mv0 * sigmoidf_(accg[m][n][1] + gb1) * (accp[m][n][1] + pb1);
                    float v10 = mv1 * sigmoidf_(accg[m][n][2] + gb0) * (accp[m][n][2] + pb0);
                    float v11 = mv1 * sigmoidf_(accg[m][n][3] + gb1) * (accp[m][n][3] + pb1);
                    __half* p0 = dst + (size_t)c0 * NN + r0 + row0;
                    __half* p1 = dst + (size_t)(c0 + 1) * NN + r0 + row0;
                    p0[0] = __float2half_rn(v00);
                    p1[0] = __float2half_rn(v01);
                    p0[8] = __float2half_rn(v10);
                    p1[8] = __float2half_rn(v11);
                }
            }
        } else {
            float accg[4][2][4];
            #pragma unroll
            for (int m = 0; m < 4; m++)
                #pragma unroll
                for (int n = 0; n < 2; n++)
                    #pragma unroll
                    for (int e = 0; e < 4; e++) accg[m][n][e] = 0.f;

            #pragma unroll
            for (int kk = 0; kk < 8; kk++) {
                const uint32_t halfA = (uint32_t)(kk >> 2) * 16384u;
                const uint32_t halfW = (uint32_t)(kk >> 2) * 8192u;
                const uint32_t k32   = (uint32_t)(kk & 3) * 32u;

                uint32_t ah[4][4];
                #pragma unroll
                for (int f = 0; f < 4; f++) {
                    uint32_t off = SW128((uint32_t)((m0 + f*16 + aRow)*128) + k32 + aK);
                    ldm4(uA + halfA + off, ah[f]);
                }
                uint32_t gh[4];
                {
                    uint32_t off = SW128((uint32_t)((n0 + bRow)*128) + k32 + bK);
                    ldm4(sW0 + halfW + off, gh);
                }
                #pragma unroll
                for (int m = 0; m < 4; m++)
                    #pragma unroll
                    for (int n = 0; n < 2; n++)
                        mma16816(accg[m][n], ah[m], gh[n*2], gh[n*2+1]);
            }

            #pragma unroll
            for (int m = 0; m < 4; m++) {
                int row0 = m0 + m*16 + (lane >> 2);
                #pragma unroll
                for (int n = 0; n < 2; n++) {
                    int c0 = n0 + n*8 + (lane & 3)*2;
                    float gb0 = __ldg(ogb + ch0 + c0), gb1 = __ldg(ogb + ch0 + c0 + 1);
                    __half2 h0 = __halves2half2(
                        __float2half_rn(sigmoidf_(accg[m][n][0] + gb0)),
                        __float2half_rn(sigmoidf_(accg[m][n][1] + gb1)));
                    __half2 h1 = __halves2half2(
                        __float2half_rn(sigmoidf_(accg[m][n][2] + gb0)),
                        __float2half_rn(sigmoidf_(accg[m][n][3] + gb1)));
                    *(__half2*)(g_gate + (size_t)(r0 + row0)*DDIM + ch0 + c0)     = h0;
                    *(__half2*)(g_gate + (size_t)(r0 + row0 + 8)*DDIM + ch0 + c0) = h1;
                }
            }
        }
        __syncthreads();
    }
}

// ============================================================================
// Kernel B: 3-stage cp.async pipeline, single barrier per chunk.
// smem: 3 stages x 32KB (A 16K + B 16K) = 96KB -> 2 CTA/SM.
// ============================================================================
__global__ void __launch_bounds__(256, 2) kB()
{
    extern __shared__ char smc[];
    const uint32_t sbase = smem_u32(smc);

    const int t    = threadIdx.x;
    const int lane = t & 31;
    const int wid  = t >> 5;
    const int d    = blockIdx.z;
    const int i0   = blockIdx.x * 128;
    const int j0   = blockIdx.y * 128;

    const int m0 = (wid & 1) * 64;
    const int n0 = (wid >> 1) * 32;

    const __half* srcA = g_af + (size_t)d*NN + (size_t)i0*NSEQ;
    const __half* srcB = g_bf + (size_t)d*NN + (size_t)j0*NSEQ;

    auto issue = [&](int stage, int kc) {
        uint32_t sb = sbase + stage * 32768;
        #pragma unroll
        for (int q = 0; q < 4; q++) {
            int seg = t + 256*q;
            int row = seg >> 3;
            int s   = seg & 7;
            uint32_t off = SW128((uint32_t)(row*128 + s*16));
            CP_ASYNC16(sb + off,         srcA + (size_t)row*NSEQ + kc + s*8);
            CP_ASYNC16(sb + 16384 + off, srcB + (size_t)row*NSEQ + kc + s*8);
        }
        CP_COMMIT();
    };

    float acc[4][4][4];
    #pragma unroll
    for (int m = 0; m < 4; m++)
        #pragma unroll
        for (int n = 0; n < 4; n++)
            #pragma unroll
            for (int e = 0; e < 4; e++) acc[m][n][e] = 0.0f;

    const int aRow = lane & 15;
    const int aK   = (lane >> 4) * 16;
    const int bRow = (lane & 7) + ((lane >> 4) << 3);
    const int bK   = ((lane >> 3) & 1) * 16;

    issue(0, 0);
    issue(1, 64);

    for (int ch = 0; ch < 8; ch++) {
        const int stage = ch % 3;
        CP_WAIT(1);          // chunk ch's group complete (only ch+1 may remain)
        __syncthreads();     // all warps done reading stage (ch+2)%3 (chunk ch-1)
        if (ch + 2 < 8) issue((ch + 2) % 3, (ch + 2) * 64);

        const uint32_t sA = sbase + stage * 32768;
        const uint32_t sB = sA + 16384;

        #pragma unroll
        for (int kk = 0; kk < 4; kk++) {
            const uint32_t kOffA = (uint32_t)(kk*32) + aK;
            const uint32_t kOffB = (uint32_t)(kk*32) + bK;

            uint32_t bh[2][4];
            #pragma unroll
            for (int c = 0; c < 2; c++) {
                uint32_t off = (uint32_t)((n0 + c*16 + bRow) * 128) + kOffB;
                ldm4(sB + SW128(off), bh[c]);
            }
            uint32_t ah[4][4];
            #pragma unroll
            for (int f = 0; f < 4; f++) {
                uint32_t off = (uint32_t)((m0 + f*16 + aRow) * 128) + kOffA;
                ldm4(sA + SW128(off), ah[f]);
            }
            #pragma unroll
            for (int m = 0; m < 4; m++)
                #pragma unroll
                for (int n = 0; n < 4; n++)
                    mma16816(acc[m][n], ah[m], bh[n>>1][(n&1)*2], bh[n>>1][(n&1)*2+1]);
        }
    }

    float* base = g_t + (size_t)d*NN;
    #pragma unroll
    for (int m = 0; m < 4; m++) {
        int r1 = i0 + m0 + m*16 + (lane >> 2);
        #pragma unroll
        for (int n = 0; n < 4; n++) {
            int c = j0 + n0 + n*8 + (lane & 3)*2;
            float2 lo = make_float2(acc[m][n][0], acc[m][n][1]);
            float2 hi = make_float2(acc[m][n][2], acc[m][n][3]);
            *(float2*)(base + (size_t)r1*NSEQ + c)       = lo;
            *(float2*)(base + (size_t)(r1+8)*NSEQ + c)   = hi;
        }
    }
}

// ============================================================================
// Kernel C (LN folded into epilogue) — unchanged from R12
// ============================================================================
__global__ void __launch_bounds__(256, 2) kC(
    const float* __restrict__ opb,
    float* __restrict__ out)
{
    extern __shared__ char smc[];
    const uint32_t sbase = smem_u32(smc);
    const uint32_t uTh  = sbase;
    const uint32_t uTl  = sbase + 16384;
    const uint32_t uWph = sbase + 32768;
    float* pS    = (float*)(smc + 65536);
    float* pQ    = (float*)(smc + 65536 + 4352);
    float* sMu   = (float*)(smc + 65536 + 8704);
    float* sRstd = (float*)(smc + 65536 + 8960);

    const int t    = threadIdx.x;
    const int lane = t & 31;
    const int wid  = t >> 5;
    const int r0   = blockIdx.x * 64;

    #pragma unroll
    for (int q = 0; q < 8; q++) {
        int seg = t + 256*q;
        int ch  = seg >> 4;
        int s8  = seg & 15;
        uint32_t dst = ((s8 >= 8) ? 16384u : 0u) + SW128((uint32_t)(ch*128 + (s8 & 7)*16));
        CP_ASYNC16(uWph + dst, g_oph + (size_t)ch*128 + s8*8);
    }
    CP_COMMIT();

    const int r4 = (t & 15) * 4;
    const int gg = t >> 4;
    float s0=0.f, s1=0.f, s2=0.f, s3=0.f;
    float q0=0.f, q1=0.f, q2=0.f, q3=0.f;
    #pragma unroll
    for (int q8 = 0; q8 < 8; q8++) {
        int dd = gg + 16*q8;
        float4 f = *(const float4*)(g_t + (size_t)dd*NN + r0 + r4);
        s0 += f.x; q0 += f.x*f.x;
        s1 += f.y; q1 += f.y*f.y;
        s2 += f.z; q2 += f.z*f.z;
        s3 += f.w; q3 += f.w*f.w;
        __half h0 = __float2half_rn(f.x), h1 = __float2half_rn(f.y);
        __half h2 = __float2half_rn(f.z), h3 = __float2half_rn(f.w);
        __half l0 = __float2half_rn(f.x - __half2float(h0));
        __half l1 = __float2half_rn(f.y - __half2float(h1));
        __half l2 = __float2half_rn(f.z - __half2float(h2));
        __half l3 = __float2half_rn(f.w - __half2float(h3));
        uint32_t off = SW128((uint32_t)(dd*128 + r4*2));
        __half2 hA = __halves2half2(h0, h1), hB = __halves2half2(h2, h3);
        __half2 lA = __halves2half2(l0, l1), lB = __halves2half2(l2, l3);
        *(__half2*)(smc + off)             = hA;
        *(__half2*)(smc + off + 4)         = hB;
        *(__half2*)(smc + 16384 + off)     = lA;
        *(__half2*)(smc + 16384 + off + 4) = lB;
    }
    pS[(r4+0)*17 + gg] = s0;  pQ[(r4+0)*17 + gg] = q0;
    pS[(r4+1)*17 + gg] = s1;  pQ[(r4+1)*17 + gg] = q1;
    pS[(r4+2)*17 + gg] = s2;  pQ[(r4+2)*17 + gg] = q2;
    pS[(r4+3)*17 + gg] = s3;  pQ[(r4+3)*17 + gg] = q3;
    __syncthreads();

    if (t < 64) {
        float s = 0.f, q = 0.f;
        #pragma unroll
        for (int g = 0; g < 16; g++) { s += pS[t*17 + g]; q += pQ[t*17 + g]; }
        float mu  = s * (1.0f/128.0f);
        float var = q * (1.0f/128.0f) - mu*mu;
        sMu[t]   = mu;
        sRstd[t] = rsqrtf(var + 1e-5f);
    }
    CP_WAIT(0);
    __syncthreads();

    const int bRow = (lane & 7) + ((lane >> 4) << 3);
    const int bK   = ((lane >> 3) & 1) * 16;
    const int m0   = (wid & 1) * 32;
    const int n0   = (wid >> 1) * 32;
    const int tD = (lane & 7) + ((lane & 16) >> 1);
    const int tR = ((lane >> 3) & 1) * 8;

    float acc[2][4][4];
    #pragma unroll
    for (int m = 0; m < 2; m++)
        #pragma unroll
        for (int n = 0; n < 4; n++)
            #pragma unroll
            for (int e = 0; e < 4; e++) acc[m][n][e] = 0.f;

    #pragma unroll
    for (int kk = 0; kk < 8; kk++) {
        const int d0 = kk * 16;
        const uint32_t halfW = (uint32_t)(kk >> 2) * 16384u;
        const uint32_t k32   = (uint32_t)(kk & 3) * 32u;

        uint32_t a2h[2][4], a2l[2][4];
        #pragma unroll
        for (int f = 0; f < 2; f++) {
            uint32_t off = SW128((uint32_t)((d0 + tD)*128 + (m0 + f*16 + tR)*2));
            ldm4t(uTh + off, a2h[f]);
            ldm4t(uTl + off, a2l[f]);
        }
        uint32_t ph[2][4];
        #pragma unroll
        for (int c = 0; c < 2; c++) {
            uint32_t off = SW128((uint32_t)((n0 + c*16 + bRow)*128) + k32 + bK);
            ldm4(uWph + halfW + off, ph[c]);
        }
        #pragma unroll
        for (int m = 0; m < 2; m++)
            #pragma unroll
            for (int n = 0; n < 4; n++) {
                int ci = n >> 1, bi = (n & 1) * 2;
                mma16816(acc[m][n], a2h[m], ph[ci][bi], ph[ci][bi+1]);
                mma16816(acc[m][n], a2l[m], ph[ci][bi], ph[ci][bi+1]);
            }
    }

    #pragma unroll
    for (int m = 0; m < 2; m++) {
        int row0 = m0 + m*16 + (lane >> 2);
        float mu0 = sMu[row0],   rs0 = sRstd[row0];
        float mu1 = sMu[row0+8], rs1 = sRstd[row0+8];
        #pragma unroll
        for (int n = 0; n < 4; n++) {
            int c0 = n0 + n*8 + (lane & 3)*2;
            float pb0 = __ldg(opb + c0),    pb1 = __ldg(opb + c0 + 1);
            float wb0 = __ldg(g_wbar + c0), wb1 = __ldg(g_wbar + c0 + 1);
            __half2 gv0 = *(const __half2*)(g_gate + (size_t)(r0 + row0)*DDIM + c0);
            __half2 gv1 = *(const __half2*)(g_gate + (size_t)(r0 + row0 + 8)*DDIM + c0);
            float2 g0 = __half22float2(gv0), g1 = __half22float2(gv1);
            float2 v0, v1;
            v0.x = g0.x * (rs0 * (acc[m][n][0] - mu0*wb0) + pb0);
            v0.y = g0.y * (rs0 * (acc[m][n][1] - mu0*wb1) + pb1);
            v1.x = g1.x * (rs1 * (acc[m][n][2] - mu1*wb0) + pb0);
            v1.y = g1.y * (rs1 * (acc[m][n][3] - mu1*wb1) + pb1);
            *(float2*)(out + (size_t)(r0 + row0)*DDIM + c0)     = v0;
            *(float2*)(out + (size_t)(r0 + row0 + 8)*DDIM + c0) = v1;
        }
    }
}

// ============================================================================
extern "C" void kernel_launch(void* const* d_in, const int* in_sizes, int n_in,
                              void* d_out, int out_size)
{
    const float* pair = (const float*)d_in[0];
    const float* mask = (const float*)d_in[1];
    const float* apw  = (const float*)d_in[2];
    const float* apb  = (const float*)d_in[3];
    const float* agw  = (const float*)d_in[4];
    const float* agb  = (const float*)d_in[5];
    const float* opw  = (const float*)d_in[6];
    const float* opb  = (const float*)d_in[7];
    const float* ogw  = (const float*)d_in[8];
    const float* ogb  = (const float*)d_in[9];
    float* out = (float*)d_out;

    const size_t smA = 98816;    // 96.5 KB -> 2 CTA/SM
    const size_t smB = 98304;    // 96 KB (3 stages) -> 2 CTA/SM
    const size_t smC = 75264;    // ~73.5KB -> 2 CTA/SM
    cudaFuncSetAttribute(kA, cudaFuncAttributeMaxDynamicSharedMemorySize, (int)smA);
    cudaFuncSetAttribute(kB, cudaFuncAttributeMaxDynamicSharedMemorySize, (int)smB);
    cudaFuncSetAttribute(kC, cudaFuncAttributeMaxDynamicSharedMemorySize, (int)smC);

    kW<<<128, 256>>>(agw, apw, ogw, opw);
    kWb<<<1, 128>>>(opw);
    kA<<<NN/128, 256, smA>>>(pair, mask, apb, agb, ogb);
    kB<<<dim3(4, 4, DDIM), 256, smB>>>();
    kC<<<NN/64, 256, smC>>>(opb, out);
}

// round 16
// speedup vs baseline: 1.0818x; 1.0091x over previous
#include <cuda_runtime.h>
#include <cuda_fp16.h>
#include <cstdint>
#include <cstddef>

#define NSEQ 512
#define DDIM 128
#define NN   (NSEQ*NSEQ)

// Scratch
static __device__ __half g_af[(size_t)DDIM * NN];
static __device__ __half g_bf[(size_t)DDIM * NN];
static __device__ float  g_t[(size_t)DDIM * NN];
static __device__ __half g_gate[(size_t)NN * DDIM];

// Pre-converted weights (fp16), row-major [ch][k]
static __device__ __half g_wg[256*128];
static __device__ __half g_wp[256*128];
static __device__ __half g_og[128*128];
static __device__ __half g_oph[128*128];
static __device__ float  g_wbar[128];     // sums of fp16(opw)

__device__ __forceinline__ float sigmoidf_(float x) { return 1.0f / (1.0f + __expf(-x)); }

__device__ __forceinline__ uint32_t smem_u32(const void* p) {
    uint32_t a;
    asm("{ .reg .u64 t; cvta.to.shared.u64 t, %1; cvt.u32.u64 %0, t; }" : "=r"(a) : "l"(p));
    return a;
}
#define SW128(o) ((o) ^ (((o) >> 3) & 0x70))

#define CP_ASYNC16(dst, src) \
    asm volatile("cp.async.cg.shared.global [%0], [%1], 16;" :: "r"(dst), "l"(src) : "memory")
#define CP_COMMIT() asm volatile("cp.async.commit_group;" ::: "memory")
#define CP_WAIT(n)  asm volatile("cp.async.wait_group %0;" :: "n"(n) : "memory")

__device__ __forceinline__ void ldm4(uint32_t addr, uint32_t r[4]) {
    asm volatile("ldmatrix.sync.aligned.m8n8.x4.shared.b16 {%0,%1,%2,%3}, [%4];"
        : "=r"(r[0]), "=r"(r[1]), "=r"(r[2]), "=r"(r[3]) : "r"(addr));
}
__device__ __forceinline__ void ldm4t(uint32_t addr, uint32_t r[4]) {
    asm volatile("ldmatrix.sync.aligned.m8n8.x4.trans.shared.b16 {%0,%1,%2,%3}, [%4];"
        : "=r"(r[0]), "=r"(r[1]), "=r"(r[2]), "=r"(r[3]) : "r"(addr));
}
__device__ __forceinline__ void mma16816(float c[4], const uint32_t a[4],
                                         uint32_t b0, uint32_t b1) {
    asm volatile(
        "mma.sync.aligned.m16n8k16.row.col.f32.f16.f16.f32 "
        "{%0,%1,%2,%3}, {%4,%5,%6,%7}, {%8,%9}, {%0,%1,%2,%3};"
        : "+f"(c[0]), "+f"(c[1]), "+f"(c[2]), "+f"(c[3])
        : "r"(a[0]), "r"(a[1]), "r"(a[2]), "r"(a[3]), "r"(b0), "r"(b1));
}

// ============================================================================
__global__ void __launch_bounds__(256) kW(
    const float* __restrict__ agw, const float* __restrict__ apw,
    const float* __restrict__ ogw, const float* __restrict__ opw)
{
    int i = blockIdx.x * 256 + threadIdx.x;
    if (i < 256*128) {
        g_wg[i] = __float2half_rn(agw[i]);
        g_wp[i] = __float2half_rn(apw[i]);
    }
    if (i < 128*128) {
        g_og[i]  = __float2half_rn(ogw[i]);
        g_oph[i] = __float2half_rn(opw[i]);
    }
}
// coalesced column-sum: one block per channel, tree reduction
__global__ void __launch_bounds__(128) kWb(const float* __restrict__ opw) {
    __shared__ float red[128];
    int c = blockIdx.x;
    int d = threadIdx.x;
    float v = __half2float(__float2half_rn(opw[c*128 + d]));
    red[d] = v;
    __syncthreads();
    #pragma unroll
    for (int s = 64; s >= 32; s >>= 1) {
        if (d < s) red[d] += red[d + s];
        __syncthreads();
    }
    if (d < 32) {
        float x = red[d];
        #pragma unroll
        for (int o = 16; o > 0; o >>= 1) x += __shfl_xor_sync(0xffffffffu, x, o);
        if (d == 0) g_wbar[c] = x;
    }
}

// ============================================================================
// Kernel A — R12 version (LN shuffle prologue, W pipelined, direct stores)
// smem: A 32K @0 | W 2x32K @32768 | mask @98304
// ============================================================================
__global__ void __launch_bounds__(256, 2) kA(
    const float* __restrict__ pair, const float* __restrict__ mask,
    const float* __restrict__ apb, const float* __restrict__ agb,
    const float* __restrict__ ogb)
{
    extern __shared__ char smc[];
    const uint32_t sbase = smem_u32(smc);
    const uint32_t uA = sbase;
    const uint32_t uW = sbase + 32768;
    float* sM = (float*)(smc + 98304);

    const int t    = threadIdx.x;
    const int lane = t & 31;
    const int wid  = t >> 5;
    const int r0   = blockIdx.x * 128;

    auto prefetchW = [&](int stage, int c) {
        uint32_t sb = uW + stage * 32768;
        const __half* w0;
        const __half* w1 = nullptr;
        if (c < 4) { w0 = g_wg + (size_t)c*64*128; w1 = g_wp + (size_t)c*64*128; }
        else       { w0 = g_og + (size_t)(c - 4)*64*128; }
        #pragma unroll
        for (int q = 0; q < 4; q++) {
            int seg = t + 256*q;
            int ch  = seg >> 4;
            int s8  = seg & 15;
            uint32_t dst = ((s8 >= 8) ? 8192u : 0u) + SW128((uint32_t)(ch*128 + (s8 & 7)*16));
            CP_ASYNC16(sb + dst, w0 + (size_t)ch*128 + s8*8);
            if (w1) CP_ASYNC16(sb + 16384 + dst, w1 + (size_t)ch*128 + s8*8);
        }
        CP_COMMIT();
    };
    prefetchW(0, 0);

    if (t < 128) sM[t] = mask[r0 + t];

    // LN(pair) -> fp16 A tiles
    for (int row = wid; row < 128; row += 8) {
        const float* src = pair + (size_t)(r0 + row) * DDIM;
        float x[4] = { src[lane], src[lane+32], src[lane+64], src[lane+96] };
        float s = x[0] + x[1] + x[2] + x[3];
        #pragma unroll
        for (int o = 16; o > 0; o >>= 1) s += __shfl_xor_sync(0xffffffffu, s, o);
        float mu = s * (1.0f/128.0f);
        float d0 = x[0]-mu, d1 = x[1]-mu, d2 = x[2]-mu, d3 = x[3]-mu;
        float v = d0*d0 + d1*d1 + d2*d2 + d3*d3;
        #pragma unroll
        for (int o = 16; o > 0; o >>= 1) v += __shfl_xor_sync(0xffffffffu, v, o);
        float rstd = rsqrtf(v * (1.0f/128.0f) + 1e-5f);
        float dd[4] = { d0*rstd, d1*rstd, d2*rstd, d3*rstd };
        #pragma unroll
        for (int j = 0; j < 4; j++) {
            uint32_t off = (uint32_t)(j >= 2) * 16384u
                         + SW128((uint32_t)(row*128 + (lane + 32*(j&1))*2));
            *(__half*)(smc + off) = __float2half_rn(dd[j]);
        }
    }

    const int aRow = lane & 15;
    const int aK   = (lane >> 4) * 16;
    const int bRow = (lane & 7) + ((lane >> 4) << 3);
    const int bK   = ((lane >> 3) & 1) * 16;
    const int m0   = (wid & 1) * 64;
    const int n0   = (wid >> 1) * 16;

    for (int c = 0; c < 6; c++) {
        const int stage = c & 1;
        if (c < 5) { prefetchW(stage ^ 1, c + 1); CP_WAIT(1); }
        else       { CP_WAIT(0); }
        __syncthreads();

        const uint32_t sW0 = uW + stage * 32768;
        const uint32_t sW1 = sW0 + 16384;
        const bool isAB = (c < 4);
        const int ch0   = isAB ? c * 64 : (c - 4) * 64;

        if (isAB) {
            float accg[4][2][4], accp[4][2][4];
            #pragma unroll
            for (int m = 0; m < 4; m++)
                #pragma unroll
                for (int n = 0; n < 2; n++)
                    #pragma unroll
                    for (int e = 0; e < 4; e++) { accg[m][n][e] = 0.f; accp[m][n][e] = 0.f; }

            #pragma unroll
            for (int kk = 0; kk < 8; kk++) {
                const uint32_t halfA = (uint32_t)(kk >> 2) * 16384u;
                const uint32_t halfW = (uint32_t)(kk >> 2) * 8192u;
                const uint32_t k32   = (uint32_t)(kk & 3) * 32u;

                uint32_t ah[4][4];
                #pragma unroll
                for (int f = 0; f < 4; f++) {
                    uint32_t off = SW128((uint32_t)((m0 + f*16 + aRow)*128) + k32 + aK);
                    ldm4(uA + halfA + off, ah[f]);
                }
                uint32_t gh[4], ph[4];
                {
                    uint32_t off = SW128((uint32_t)((n0 + bRow)*128) + k32 + bK);
                    ldm4(sW0 + halfW + off, gh);
                    ldm4(sW1 + halfW + off, ph);
                }
                #pragma unroll
                for (int m = 0; m < 4; m++)
                    #pragma unroll
                    for (int n = 0; n < 2; n++) {
                        mma16816(accg[m][n], ah[m], gh[n*2], gh[n*2+1]);
                        mma16816(accp[m][n], ah[m], ph[n*2], ph[n*2+1]);
                    }
            }

            __half* dst = (ch0 < 128) ? (g_af + (size_t)ch0 * NN)
                                      : (g_bf + (size_t)(ch0 - 128) * NN);
            #pragma unroll
            for (int m = 0; m < 4; m++) {
                int row0 = m0 + m*16 + (lane >> 2);
                #pragma unroll
                for (int n = 0; n < 2; n++) {
                    int c0 = n0 + n*8 + (lane & 3)*2;
                    float gb0 = __ldg(agb + ch0 + c0), gb1 = __ldg(agb + ch0 + c0 + 1);
                    float pb0 = __ldg(apb + ch0 + c0), pb1 = __ldg(apb + ch0 + c0 + 1);
                    float mv0 = sM[row0], mv1 = sM[row0 + 8];
                    float v00 = mv0 * sigmoidf_(accg[m][n][0] + gb0) * (accp[m][n][0] + pb0);
                    float v01 = mv0 * sigmoidf_(accg[m][n][1] + gb1) * (accp[m][n][1] + pb1);
                    float v10 = mv1 * sigmoidf_(accg[m][n][2] + gb0) * (accp[m][n][2] + pb0);
                    float v11 = mv1 * sigmoidf_(accg[m][n][3] + gb1) * (accp[m][n][3] + pb1);
                    __half* p0 = dst + (size_t)c0 * NN + r0 + row0;
                    __half* p1 = dst + (size_t)(c0 + 1) * NN + r0 + row0;
                    p0[0] = __float2half_rn(v00);
                    p1[0] = __float2half_rn(v01);
                    p0[8] = __float2half_rn(v10);
                    p1[8] = __float2half_rn(v11);
                }
            }
        } else {
            float accg[4][2][4];
            #pragma unroll
            for (int m = 0; m < 4; m++)
                #pragma unroll
                for (int n = 0; n < 2; n++)
                    #pragma unroll
                    for (int e = 0; e < 4; e++) accg[m][n][e] = 0.f;

            #pragma unroll
            for (int kk = 0; kk < 8; kk++) {
                const uint32_t halfA = (uint32_t)(kk >> 2) * 16384u;
                const uint32_t halfW = (uint32_t)(kk >> 2) * 8192u;
                const uint32_t k32   = (uint32_t)(kk & 3) * 32u;

                uint32_t ah[4][4];
                #pragma unroll
                for (int f = 0; f < 4; f++) {
                    uint32_t off = SW128((uint32_t)((m0 + f*16 + aRow)*128) + k32 + aK);
                    ldm4(uA + halfA + off, ah[f]);
                }
                uint32_t gh[4];
                {
                    uint32_t off = SW128((uint32_t)((n0 + bRow)*128) + k32 + bK);
                    ldm4(sW0 + halfW + off, gh);
                }
                #pragma unroll
                for (int m = 0; m < 4; m++)
                    #pragma unroll
                    for (int n = 0; n < 2; n++)
                        mma16816(accg[m][n], ah[m], gh[n*2], gh[n*2+1]);
            }

            #pragma unroll
            for (int m = 0; m < 4; m++) {
                int row0 = m0 + m*16 + (lane >> 2);
                #pragma unroll
                for (int n = 0; n < 2; n++) {
                    int c0 = n0 + n*8 + (lane & 3)*2;
                    float gb0 = __ldg(ogb + ch0 + c0), gb1 = __ldg(ogb + ch0 + c0 + 1);
                    __half2 h0 = __halves2half2(
                        __float2half_rn(sigmoidf_(accg[m][n][0] + gb0)),
                        __float2half_rn(sigmoidf_(accg[m][n][1] + gb1)));
                    __half2 h1 = __halves2half2(
                        __float2half_rn(sigmoidf_(accg[m][n][2] + gb0)),
                        __float2half_rn(sigmoidf_(accg[m][n][3] + gb1)));
                    *(__half2*)(g_gate + (size_t)(r0 + row0)*DDIM + ch0 + c0)     = h0;
                    *(__half2*)(g_gate + (size_t)(r0 + row0 + 8)*DDIM + ch0 + c0) = h1;
                }
            }
        }
        __syncthreads();
    }
}

// ============================================================================
// Kernel B: 3-stage cp.async pipeline (R15)
// ============================================================================
__global__ void __launch_bounds__(256, 2) kB()
{
    extern __shared__ char smc[];
    const uint32_t sbase = smem_u32(smc);

    const int t    = threadIdx.x;
    const int lane = t & 31;
    const int wid  = t >> 5;
    const int d    = blockIdx.z;
    const int i0   = blockIdx.x * 128;
    const int j0   = blockIdx.y * 128;

    const int m0 = (wid & 1) * 64;
    const int n0 = (wid >> 1) * 32;

    const __half* srcA = g_af + (size_t)d*NN + (size_t)i0*NSEQ;
    const __half* srcB = g_bf + (size_t)d*NN + (size_t)j0*NSEQ;

    auto issue = [&](int stage, int kc) {
        uint32_t sb = sbase + stage * 32768;
        #pragma unroll
        for (int q = 0; q < 4; q++) {
            int seg = t + 256*q;
            int row = seg >> 3;
            int s   = seg & 7;
            uint32_t off = SW128((uint32_t)(row*128 + s*16));
            CP_ASYNC16(sb + off,         srcA + (size_t)row*NSEQ + kc + s*8);
            CP_ASYNC16(sb + 16384 + off, srcB + (size_t)row*NSEQ + kc + s*8);
        }
        CP_COMMIT();
    };

    float acc[4][4][4];
    #pragma unroll
    for (int m = 0; m < 4; m++)
        #pragma unroll
        for (int n = 0; n < 4; n++)
            #pragma unroll
            for (int e = 0; e < 4; e++) acc[m][n][e] = 0.0f;

    const int aRow = lane & 15;
    const int aK   = (lane >> 4) * 16;
    const int bRow = (lane & 7) + ((lane >> 4) << 3);
    const int bK   = ((lane >> 3) & 1) * 16;

    issue(0, 0);
    issue(1, 64);

    for (int ch = 0; ch < 8; ch++) {
        const int stage = ch % 3;
        CP_WAIT(1);
        __syncthreads();
        if (ch + 2 < 8) issue((ch + 2) % 3, (ch + 2) * 64);

        const uint32_t sA = sbase + stage * 32768;
        const uint32_t sB = sA + 16384;

        #pragma unroll
        for (int kk = 0; kk < 4; kk++) {
            const uint32_t kOffA = (uint32_t)(kk*32) + aK;
            const uint32_t kOffB = (uint32_t)(kk*32) + bK;

            uint32_t bh[2][4];
            #pragma unroll
            for (int c = 0; c < 2; c++) {
                uint32_t off = (uint32_t)((n0 + c*16 + bRow) * 128) + kOffB;
                ldm4(sB + SW128(off), bh[c]);
            }
            uint32_t ah[4][4];
            #pragma unroll
            for (int f = 0; f < 4; f++) {
                uint32_t off = (uint32_t)((m0 + f*16 + aRow) * 128) + kOffA;
                ldm4(sA + SW128(off), ah[f]);
            }
            #pragma unroll
            for (int m = 0; m < 4; m++)
                #pragma unroll
                for (int n = 0; n < 4; n++)
                    mma16816(acc[m][n], ah[m], bh[n>>1][(n&1)*2], bh[n>>1][(n&1)*2+1]);
        }
    }

    float* base = g_t + (size_t)d*NN;
    #pragma unroll
    for (int m = 0; m < 4; m++) {
        int r1 = i0 + m0 + m*16 + (lane >> 2);
        #pragma unroll
        for (int n = 0; n < 4; n++) {
            int c = j0 + n0 + n*8 + (lane & 3)*2;
            float2 lo = make_float2(acc[m][n][0], acc[m][n][1]);
            float2 hi = make_float2(acc[m][n][2], acc[m][n][3]);
            *(float2*)(base + (size_t)r1*NSEQ + c)       = lo;
            *(float2*)(base + (size_t)(r1+8)*NSEQ + c)   = hi;
        }
    }
}

// ============================================================================
// Kernel C (LN folded into epilogue) — unchanged
// ============================================================================
__global__ void __launch_bounds__(256, 2) kC(
    const float* __restrict__ opb,
    float* __restrict__ out)
{
    extern __shared__ char smc[];
    const uint32_t sbase = smem_u32(smc);
    const uint32_t uTh  = sbase;
    const uint32_t uTl  = sbase + 16384;
    const uint32_t uWph = sbase + 32768;
    float* pS    = (float*)(smc + 65536);
    float* pQ    = (float*)(smc + 65536 + 4352);
    float* sMu   = (float*)(smc + 65536 + 8704);
    float* sRstd = (float*)(smc + 65536 + 8960);

    const int t    = threadIdx.x;
    const int lane = t & 31;
    const int wid  = t >> 5;
    const int r0   = blockIdx.x * 64;

    #pragma unroll
    for (int q = 0; q < 8; q++) {
        int seg = t + 256*q;
        int ch  = seg >> 4;
        int s8  = seg & 15;
        uint32_t dst = ((s8 >= 8) ? 16384u : 0u) + SW128((uint32_t)(ch*128 + (s8 & 7)*16));
        CP_ASYNC16(uWph + dst, g_oph + (size_t)ch*128 + s8*8);
    }
    CP_COMMIT();

    const int r4 = (t & 15) * 4;
    const int gg = t >> 4;
    float s0=0.f, s1=0.f, s2=0.f, s3=0.f;
    float q0=0.f, q1=0.f, q2=0.f, q3=0.f;
    #pragma unroll
    for (int q8 = 0; q8 < 8; q8++) {
        int dd = gg + 16*q8;
        float4 f = *(const float4*)(g_t + (size_t)dd*NN + r0 + r4);
        s0 += f.x; q0 += f.x*f.x;
        s1 += f.y; q1 += f.y*f.y;
        s2 += f.z; q2 += f.z*f.z;
        s3 += f.w; q3 += f.w*f.w;
        __half h0 = __float2half_rn(f.x), h1 = __float2half_rn(f.y);
        __half h2 = __float2half_rn(f.z), h3 = __float2half_rn(f.w);
        __half l0 = __float2half_rn(f.x - __half2float(h0));
        __half l1 = __float2half_rn(f.y - __half2float(h1));
        __half l2 = __float2half_rn(f.z - __half2float(h2));
        __half l3 = __float2half_rn(f.w - __half2float(h3));
        uint32_t off = SW128((uint32_t)(dd*128 + r4*2));
        __half2 hA = __halves2half2(h0, h1), hB = __halves2half2(h2, h3);
        __half2 lA = __halves2half2(l0, l1), lB = __halves2half2(l2, l3);
        *(__half2*)(smc + off)             = hA;
        *(__half2*)(smc + off + 4)         = hB;
        *(__half2*)(smc + 16384 + off)     = lA;
        *(__half2*)(smc + 16384 + off + 4) = lB;
    }
    pS[(r4+0)*17 + gg] = s0;  pQ[(r4+0)*17 + gg] = q0;
    pS[(r4+1)*17 + gg] = s1;  pQ[(r4+1)*17 + gg] = q1;
    pS[(r4+2)*17 + gg] = s2;  pQ[(r4+2)*17 + gg] = q2;
    pS[(r4+3)*17 + gg] = s3;  pQ[(r4+3)*17 + gg] = q3;
    __syncthreads();

    if (t < 64) {
        float s = 0.f, q = 0.f;
        #pragma unroll
        for (int g = 0; g < 16; g++) { s += pS[t*17 + g]; q += pQ[t*17 + g]; }
        float mu  = s * (1.0f/128.0f);
        float var = q * (1.0f/128.0f) - mu*mu;
        sMu[t]   = mu;
        sRstd[t] = rsqrtf(var + 1e-5f);
    }
    CP_WAIT(0);
    __syncthreads();

    const int bRow = (lane & 7) + ((lane >> 4) << 3);
    const int bK   = ((lane >> 3) & 1) * 16;
    const int m0   = (wid & 1) * 32;
    const int n0   = (wid >> 1) * 32;
    const int tD = (lane & 7) + ((lane & 16) >> 1);
    const int tR = ((lane >> 3) & 1) * 8;

    float acc[2][4][4];
    #pragma unroll
    for (int m = 0; m < 2; m++)
        #pragma unroll
        for (int n = 0; n < 4; n++)
            #pragma unroll
            for (int e = 0; e < 4; e++) acc[m][n][e] = 0.f;

    #pragma unroll
    for (int kk = 0; kk < 8; kk++) {
        const int d0 = kk * 16;
        const uint32_t halfW = (uint32_t)(kk >> 2) * 16384u;
        const uint32_t k32   = (uint32_t)(kk & 3) * 32u;

        uint32_t a2h[2][4], a2l[2][4];
        #pragma unroll
        for (int f = 0; f < 2; f++) {
            uint32_t off = SW128((uint32_t)((d0 + tD)*128 + (m0 + f*16 + tR)*2));
            ldm4t(uTh + off, a2h[f]);
            ldm4t(uTl + off, a2l[f]);
        }
        uint32_t ph[2][4];
        #pragma unroll
        for (int c = 0; c < 2; c++) {
            uint32_t off = SW128((uint32_t)((n0 + c*16 + bRow)*128) + k32 + bK);
            ldm4(uWph + halfW + off, ph[c]);
        }
        #pragma unroll
        for (int m = 0; m < 2; m++)
            #pragma unroll
            for (int n = 0; n < 4; n++) {
                int ci = n >> 1, bi = (n & 1) * 2;
                mma16816(acc[m][n], a2h[m], ph[ci][bi], ph[ci][bi+1]);
                mma16816(acc[m][n], a2l[m], ph[ci][bi], ph[ci][bi+1]);
            }
    }

    #pragma unroll
    for (int m = 0; m < 2; m++) {
        int row0 = m0 + m*16 + (lane >> 2);
        float mu0 = sMu[row0],   rs0 = sRstd[row0];
        float mu1 = sMu[row0+8], rs1 = sRstd[row0+8];
        #pragma unroll
        for (int n = 0; n < 4; n++) {
            int c0 = n0 + n*8 + (lane & 3)*2;
            float pb0 = __ldg(opb + c0),    pb1 = __ldg(opb + c0 + 1);
            float wb0 = __ldg(g_wbar + c0), wb1 = __ldg(g_wbar + c0 + 1);
            __half2 gv0 = *(const __half2*)(g_gate + (size_t)(r0 + row0)*DDIM + c0);
            __half2 gv1 = *(const __half2*)(g_gate + (size_t)(r0 + row0 + 8)*DDIM + c0);
            float2 g0 = __half22float2(gv0), g1 = __half22float2(gv1);
            float2 v0, v1;
            v0.x = g0.x * (rs0 * (acc[m][n][0] - mu0*wb0) + pb0);
            v0.y = g0.y * (rs0 * (acc[m][n][1] - mu0*wb1) + pb1);
            v1.x = g1.x * (rs1 * (acc[m][n][2] - mu1*wb0) + pb0);
            v1.y = g1.y * (rs1 * (acc[m][n][3] - mu1*wb1) + pb1);
            *(float2*)(out + (size_t)(r0 + row0)*DDIM + c0)     = v0;
            *(float2*)(out + (size_t)(r0 + row0 + 8)*DDIM + c0) = v1;
        }
    }
}

// ============================================================================
extern "C" void kernel_launch(void* const* d_in, const int* in_sizes, int n_in,
                              void* d_out, int out_size)
{
    const float* pair = (const float*)d_in[0];
    const float* mask = (const float*)d_in[1];
    const float* apw  = (const float*)d_in[2];
    const float* apb  = (const float*)d_in[3];
    const float* agw  = (const float*)d_in[4];
    const float* agb  = (const float*)d_in[5];
    const float* opw  = (const float*)d_in[6];
    const float* opb  = (const float*)d_in[7];
    const float* ogw  = (const float*)d_in[8];
    const float* ogb  = (const float*)d_in[9];
    float* out = (float*)d_out;

    const size_t smA = 98816;    // 96.5 KB -> 2 CTA/SM
    const size_t smB = 98304;    // 96 KB (3 stages) -> 2 CTA/SM
    const size_t smC = 75264;    // ~73.5KB -> 2 CTA/SM
    cudaFuncSetAttribute(kA, cudaFuncAttributeMaxDynamicSharedMemorySize, (int)smA);
    cudaFuncSetAttribute(kB, cudaFuncAttributeMaxDynamicSharedMemorySize, (int)smB);
    cudaFuncSetAttribute(kC, cudaFuncAttributeMaxDynamicSharedMemorySize, (int)smC);

    kW<<<128, 256>>>(agw, apw, ogw, opw);
    kWb<<<128, 128>>>(opw);
    kA<<<NN/128, 256, smA>>>(pair, mask, apb, agb, ogb);
    kB<<<dim3(4, 4, DDIM), 256, smB>>>();
    kC<<<NN/64, 256, smC>>>(opb, out);
}